// round 1
// baseline (speedup 1.0000x reference)
#include <cuda_runtime.h>

#define NB    16
#define SEQ   512
#define MTOK  (NB*SEQ)     // 8192 tokens
#define EDIM  768
#define HDIM  1024
#define NLANG 5

// ---- scratch (static device globals; allocation-free) ----
__device__ float d_nerT[MTOK*HDIM];   // ner transform (pre-LN, then LN'd in place)
__device__ float d_topT[MTOK*HDIM];   // topic transform
__device__ float d_hid [MTOK*HDIM];   // gate hidden
__device__ int   d_lang[NB];

// ---- decode language ids (handles int32 or int64 storage) ----
__global__ void k_decode_lang(const int* __restrict__ lp) {
    if (threadIdx.x == 0 && blockIdx.x == 0) {
        int m = 0;
        #pragma unroll
        for (int i = 1; i < 16; i += 2) m |= lp[i];
        bool is64 = (m == 0);   // int64 little-endian: high words of first 8 entries are 0
        for (int b = 0; b < NB; b++) d_lang[b] = is64 ? lp[2*b] : lp[b];
    }
}

// ---- block reduction over 256 threads ----
__device__ __forceinline__ float blockSum256(float v) {
    #pragma unroll
    for (int o = 16; o > 0; o >>= 1) v += __shfl_xor_sync(0xffffffffu, v, o);
    __shared__ float sh[8];
    int w = threadIdx.x >> 5, l = threadIdx.x & 31;
    if (l == 0) sh[w] = v;
    __syncthreads();
    if (w == 0) {
        float x = (l < 8) ? sh[l] : 0.f;
        #pragma unroll
        for (int o = 4; o > 0; o >>= 1) x += __shfl_xor_sync(0xffffffffu, x, o);
        if (l == 0) sh[0] = x;
    }
    __syncthreads();
    float r = sh[0];
    __syncthreads();
    return r;
}

// ---- 128x128x8 fp32 GEMM: C[M,1024] = A[M,K] @ W[K,1024] + bias ----
__global__ void __launch_bounds__(256) k_sgemm_bias(
    const float* __restrict__ A, const float* __restrict__ W,
    const float* __restrict__ bias, float* __restrict__ C, int K)
{
    __shared__ float As[8][128];
    __shared__ float Bs[8][128];
    const int tid = threadIdx.x;
    const int bx = blockIdx.x, by = blockIdx.y;
    const int rowA = tid >> 1,  colA = (tid & 1) * 4;
    const int rowB = tid >> 5,  colB = (tid & 31) * 4;
    const int tr = (tid >> 4) * 8, tc = (tid & 15) * 8;
    const float* Ap = A + (size_t)(by*128 + rowA) * K + colA;
    const float* Wp = W + (size_t)rowB * HDIM + bx*128 + colB;
    float acc[8][8] = {};
    for (int k0 = 0; k0 < K; k0 += 8) {
        float4 av = *(const float4*)(Ap + k0);
        As[colA+0][rowA] = av.x; As[colA+1][rowA] = av.y;
        As[colA+2][rowA] = av.z; As[colA+3][rowA] = av.w;
        *(float4*)&Bs[rowB][colB] = *(const float4*)(Wp + (size_t)k0 * HDIM);
        __syncthreads();
        #pragma unroll
        for (int kk = 0; kk < 8; kk++) {
            float4 a0 = *(const float4*)&As[kk][tr];
            float4 a1 = *(const float4*)&As[kk][tr+4];
            float4 b0 = *(const float4*)&Bs[kk][tc];
            float4 b1 = *(const float4*)&Bs[kk][tc+4];
            float ra[8] = {a0.x,a0.y,a0.z,a0.w,a1.x,a1.y,a1.z,a1.w};
            float rb[8] = {b0.x,b0.y,b0.z,b0.w,b1.x,b1.y,b1.z,b1.w};
            #pragma unroll
            for (int i = 0; i < 8; i++)
                #pragma unroll
                for (int j = 0; j < 8; j++) acc[i][j] += ra[i]*rb[j];
        }
        __syncthreads();
    }
    float bv[8];
    #pragma unroll
    for (int j = 0; j < 8; j++) bv[j] = bias[bx*128 + tc + j];
    #pragma unroll
    for (int i = 0; i < 8; i++) {
        float* Cp = C + (size_t)(by*128 + tr + i) * HDIM + bx*128 + tc;
        float4 o0 = {acc[i][0]+bv[0], acc[i][1]+bv[1], acc[i][2]+bv[2], acc[i][3]+bv[3]};
        float4 o1 = {acc[i][4]+bv[4], acc[i][5]+bv[5], acc[i][6]+bv[6], acc[i][7]+bv[7]};
        *(float4*)Cp = o0; *(float4*)(Cp + 4) = o1;
    }
}

// ---- in-place LayerNorm + ReLU over rows of 1024 ----
__global__ void __launch_bounds__(256) k_ln_relu(
    float* __restrict__ buf, const float* __restrict__ gamma, const float* __restrict__ beta)
{
    const int row = blockIdx.x;
    float* x = buf + (size_t)row * HDIM;
    const int t = threadIdx.x;
    float4 v = *(const float4*)(x + t*4);
    float s  = blockSum256(v.x + v.y + v.z + v.w);
    float mu = s * (1.f / HDIM);
    float d0 = v.x-mu, d1 = v.y-mu, d2 = v.z-mu, d3 = v.w-mu;
    float sq = blockSum256(d0*d0 + d1*d1 + d2*d2 + d3*d3);
    float inv = rsqrtf(sq * (1.f / HDIM) + 1e-5f);
    float4 g = *(const float4*)(gamma + t*4);
    float4 b = *(const float4*)(beta  + t*4);
    float4 o;
    o.x = fmaxf(d0*inv*g.x + b.x, 0.f);
    o.y = fmaxf(d1*inv*g.y + b.y, 0.f);
    o.z = fmaxf(d2*inv*g.z + b.z, 0.f);
    o.w = fmaxf(d3*inv*g.w + b.w, 0.f);
    *(float4*)(x + t*4) = o;
}

// ---- gate GEMM: hid[M,1024] = [nerT | topT] @ Wg1[lang] + bg1[lang] ----
// Only the batch's own language is computed (mask-select is exact).
__global__ void __launch_bounds__(256) k_gate_gemm(
    const float* __restrict__ Wg1, const float* __restrict__ bg1,
    float* __restrict__ C)
{
    const int tid = threadIdx.x;
    const int bx = blockIdx.x, by = blockIdx.y;
    const int lang = d_lang[(by*128) / SEQ];
    const float* W  = Wg1 + (size_t)lang * 2 * HDIM * HDIM;
    const float* bb = bg1 + (size_t)lang * HDIM;
    __shared__ float As[8][128];
    __shared__ float Bs[8][128];
    const int rowA = tid >> 1,  colA = (tid & 1) * 4;
    const int rowB = tid >> 5,  colB = (tid & 31) * 4;
    const int tr = (tid >> 4) * 8, tc = (tid & 15) * 8;
    const int arow = by*128 + rowA;
    float acc[8][8] = {};
    for (int k0 = 0; k0 < 2*HDIM; k0 += 8) {
        const float* Ab = (k0 < HDIM) ? d_nerT : d_topT;
        const int kc = (k0 < HDIM) ? k0 : (k0 - HDIM);
        float4 av = *(const float4*)(Ab + (size_t)arow * HDIM + kc + colA);
        As[colA+0][rowA] = av.x; As[colA+1][rowA] = av.y;
        As[colA+2][rowA] = av.z; As[colA+3][rowA] = av.w;
        *(float4*)&Bs[rowB][colB] =
            *(const float4*)(W + (size_t)(k0 + rowB) * HDIM + bx*128 + colB);
        __syncthreads();
        #pragma unroll
        for (int kk = 0; kk < 8; kk++) {
            float4 a0 = *(const float4*)&As[kk][tr];
            float4 a1 = *(const float4*)&As[kk][tr+4];
            float4 b0 = *(const float4*)&Bs[kk][tc];
            float4 b1 = *(const float4*)&Bs[kk][tc+4];
            float ra[8] = {a0.x,a0.y,a0.z,a0.w,a1.x,a1.y,a1.z,a1.w};
            float rb[8] = {b0.x,b0.y,b0.z,b0.w,b1.x,b1.y,b1.z,b1.w};
            #pragma unroll
            for (int i = 0; i < 8; i++)
                #pragma unroll
                for (int j = 0; j < 8; j++) acc[i][j] += ra[i]*rb[j];
        }
        __syncthreads();
    }
    float bv[8];
    #pragma unroll
    for (int j = 0; j < 8; j++) bv[j] = bb[bx*128 + tc + j];
    #pragma unroll
    for (int i = 0; i < 8; i++) {
        float* Cp = C + (size_t)(by*128 + tr + i) * HDIM + bx*128 + tc;
        float4 o0 = {acc[i][0]+bv[0], acc[i][1]+bv[1], acc[i][2]+bv[2], acc[i][3]+bv[3]};
        float4 o1 = {acc[i][4]+bv[4], acc[i][5]+bv[5], acc[i][6]+bv[6], acc[i][7]+bv[7]};
        *(float4*)Cp = o0; *(float4*)(Cp + 4) = o1;
    }
}

// ---- final: LN+ReLU(hid) -> dot Wg2 -> sigmoid gates -> gate ner/top, write out ----
__global__ void __launch_bounds__(256) k_gate_finish(
    const float* __restrict__ gg, const float* __restrict__ bgv,
    const float* __restrict__ Wg2, const float* __restrict__ bg2,
    float* __restrict__ out)
{
    const int row  = blockIdx.x;
    const int lang = d_lang[row / SEQ];
    const int t    = threadIdx.x;
    const float* x = d_hid + (size_t)row * HDIM;
    float4 v = *(const float4*)(x + t*4);
    float s  = blockSum256(v.x + v.y + v.z + v.w);
    float mu = s * (1.f / HDIM);
    float d0 = v.x-mu, d1 = v.y-mu, d2 = v.z-mu, d3 = v.w-mu;
    float sq = blockSum256(d0*d0 + d1*d1 + d2*d2 + d3*d3);
    float inv = rsqrtf(sq * (1.f / HDIM) + 1e-5f);
    float4 g = *(const float4*)(gg  + (size_t)lang*HDIM + t*4);
    float4 b = *(const float4*)(bgv + (size_t)lang*HDIM + t*4);
    float h0 = fmaxf(d0*inv*g.x + b.x, 0.f);
    float h1 = fmaxf(d1*inv*g.y + b.y, 0.f);
    float h2 = fmaxf(d2*inv*g.z + b.z, 0.f);
    float h3 = fmaxf(d3*inv*g.w + b.w, 0.f);
    // Wg2: [L, H, 2] row-major
    const float* w2 = Wg2 + (size_t)lang * HDIM * 2 + (size_t)t * 8;
    float4 wa = *(const float4*)(w2);      // h+0:k0,k1 ; h+1:k0,k1
    float4 wb = *(const float4*)(w2 + 4);  // h+2:k0,k1 ; h+3:k0,k1
    float s0 = h0*wa.x + h1*wa.z + h2*wb.x + h3*wb.z;
    float s1 = h0*wa.y + h1*wa.w + h2*wb.y + h3*wb.w;
    s0 = blockSum256(s0);
    s1 = blockSum256(s1);
    float g0 = 1.f / (1.f + expf(-(s0 + bg2[lang*2 + 0])));
    float g1 = 1.f / (1.f + expf(-(s1 + bg2[lang*2 + 1])));
    size_t off = (size_t)row * HDIM + (size_t)t * 4;
    float4 nv = *(const float4*)(d_nerT + off);
    float4 tv = *(const float4*)(d_topT + off);
    float4 on = {nv.x*g0, nv.y*g0, nv.z*g0, nv.w*g0};
    float4 ot = {tv.x*g1, tv.y*g1, tv.z*g1, tv.w*g1};
    *(float4*)(out + off) = on;
    *(float4*)(out + (size_t)MTOK*HDIM + off) = ot;
}

extern "C" void kernel_launch(void* const* d_in, const int* in_sizes, int n_in,
                              void* d_out, int out_size)
{
    const float* ner    = (const float*)d_in[0];
    const float* topf   = (const float*)d_in[1];
    const int*   lang   = (const int*)d_in[2];
    const float* W_ner  = (const float*)d_in[3];
    const float* b_ner  = (const float*)d_in[4];
    const float* g_ner  = (const float*)d_in[5];
    const float* be_ner = (const float*)d_in[6];
    const float* W_top  = (const float*)d_in[7];
    const float* b_top  = (const float*)d_in[8];
    const float* g_top  = (const float*)d_in[9];
    const float* be_top = (const float*)d_in[10];
    const float* Wg1    = (const float*)d_in[11];
    const float* bg1    = (const float*)d_in[12];
    const float* gg     = (const float*)d_in[13];
    const float* bg     = (const float*)d_in[14];
    const float* Wg2    = (const float*)d_in[15];
    const float* bg2    = (const float*)d_in[16];
    float* out = (float*)d_out;

    float *pNer = nullptr, *pTop = nullptr, *pHid = nullptr;
    cudaGetSymbolAddress((void**)&pNer, d_nerT);
    cudaGetSymbolAddress((void**)&pTop, d_topT);
    cudaGetSymbolAddress((void**)&pHid, d_hid);

    k_decode_lang<<<1, 32>>>(lang);

    dim3 grid(HDIM/128, MTOK/128);  // (8, 64)
    k_sgemm_bias<<<grid, 256>>>(ner,  W_ner, b_ner, pNer, EDIM);
    k_sgemm_bias<<<grid, 256>>>(topf, W_top, b_top, pTop, EDIM);

    k_ln_relu<<<MTOK, 256>>>(pNer, g_ner, be_ner);
    k_ln_relu<<<MTOK, 256>>>(pTop, g_top, be_top);

    k_gate_gemm<<<grid, 256>>>(Wg1, bg1, pHid);

    k_gate_finish<<<MTOK, 256>>>(gg, bg, Wg2, bg2, out);
}

// round 2
// speedup vs baseline: 2.5203x; 2.5203x over previous
#include <cuda_runtime.h>

#define NB    16
#define SEQ   512
#define MTOK  (NB*SEQ)     // 8192 tokens
#define EDIM  768
#define HDIM  1024
#define NLANG 5

// ---- scratch (static device globals; allocation-free) ----
__device__ float d_nerT[MTOK*HDIM];
__device__ float d_topT[MTOK*HDIM];
__device__ float d_hid [MTOK*HDIM];
__device__ int   d_lang[NB];

// ---- decode language ids (handles int32 or int64 storage) ----
__global__ void k_decode_lang(const int* __restrict__ lp) {
    if (threadIdx.x == 0 && blockIdx.x == 0) {
        int m = 0;
        #pragma unroll
        for (int i = 1; i < 16; i += 2) m |= lp[i];
        bool is64 = (m == 0);
        for (int b = 0; b < NB; b++) d_lang[b] = is64 ? lp[2*b] : lp[b];
    }
}

// ---- helpers ----
__device__ __forceinline__ unsigned f2tf(float x) {
    unsigned y; asm("cvt.rna.tf32.f32 %0, %1;" : "=r"(y) : "f"(x)); return y;
}
__device__ __forceinline__ void mma_tf32(float (&d)[4], const unsigned (&a)[4], const unsigned (&b)[2]) {
    asm volatile("mma.sync.aligned.m16n8k8.row.col.f32.tf32.tf32.f32 "
        "{%0,%1,%2,%3}, {%4,%5,%6,%7}, {%8,%9}, {%0,%1,%2,%3};\n"
        : "+f"(d[0]), "+f"(d[1]), "+f"(d[2]), "+f"(d[3])
        : "r"(a[0]), "r"(a[1]), "r"(a[2]), "r"(a[3]), "r"(b[0]), "r"(b[1]));
}
#define CP16(dst, src) asm volatile("cp.async.cg.shared.global [%0], [%1], 16;\n"::"r"(dst),"l"(src))
#define CP_COMMIT()    asm volatile("cp.async.commit_group;\n")
#define CP_WAIT(n)     asm volatile("cp.async.wait_group %0;\n"::"n"(n))

// smem layout constants (floats)
#define AS_LD  36          // A tile: [128][36] (pad 32->36, conflict-free)
#define BS_LD  136         // B tile: [32][136] (pad 128->136, conflict-free)
#define AS_SZ  (128*AS_LD) // 4608
#define BS_SZ  (32*BS_LD)  // 4352
#define SMEM_BYTES ((AS_SZ + BS_SZ) * 2 * 4)  // 71680

// ---- TF32 tensor-core GEMM: C[M,1024] = A[M,K] @ W[K,1024] + bias ----
// GATE=true: A = [d_nerT | d_topT] (virtual concat, K=2048), W/bias selected per-language.
template<bool GATE>
__global__ void __launch_bounds__(256) k_mm_tf32(
    const float* __restrict__ A0, const float* __restrict__ W0,
    const float* __restrict__ bias0, float* __restrict__ C, int Kdim)
{
    extern __shared__ float smp[];
    float* Asm[2] = { smp, smp + AS_SZ };
    float* Bsm[2] = { smp + 2*AS_SZ, smp + 2*AS_SZ + BS_SZ };

    const int tid = threadIdx.x;
    const int bx = blockIdx.x, by = blockIdx.y;
    const int lane = tid & 31, w = tid >> 5;
    const int wm = (w & 3) * 32, wn = (w >> 2) * 64;

    const float* W    = W0;
    const float* bias = bias0;
    if (GATE) {
        int lang = d_lang[(by * 128) / SEQ];
        W    = W0    + (size_t)lang * 2 * HDIM * HDIM;
        bias = bias0 + (size_t)lang * HDIM;
    }
    const int K = GATE ? 2 * HDIM : Kdim;

    auto loadTiles = [&](int kc, int stage) {
        #pragma unroll
        for (int i = 0; i < 4; i++) {
            int chunk = tid + i * 256;
            // A: 128 rows x 32 cols, 8 chunks of 16B per row
            int row = chunk >> 3, kcol = (chunk & 7) * 4;
            const float* srcA;
            if (GATE) {
                const float* Ab = (kc < HDIM) ? d_nerT : d_topT;
                int kk = (kc < HDIM) ? kc : kc - HDIM;
                srcA = Ab + (size_t)(by*128 + row) * HDIM + kk + kcol;
            } else {
                srcA = A0 + (size_t)(by*128 + row) * Kdim + kc + kcol;
            }
            unsigned dA = (unsigned)__cvta_generic_to_shared(Asm[stage] + row*AS_LD + kcol);
            CP16(dA, srcA);
            // B: 32 rows x 128 cols, 32 chunks of 16B per row
            int krow = chunk >> 5, ncol = (chunk & 31) * 4;
            const float* srcB = W + (size_t)(kc + krow) * HDIM + bx*128 + ncol;
            unsigned dB = (unsigned)__cvta_generic_to_shared(Bsm[stage] + krow*BS_LD + ncol);
            CP16(dB, srcB);
        }
    };

    float acc[2][8][4] = {};

    const int NK = K / 32;
    loadTiles(0, 0);
    CP_COMMIT();

    for (int it = 0; it < NK; it++) {
        int cur = it & 1;
        if (it + 1 < NK) {
            loadTiles((it + 1) * 32, cur ^ 1);
            CP_COMMIT();
            CP_WAIT(1);
        } else {
            CP_WAIT(0);
        }
        __syncthreads();
        const float* Ac = Asm[cur];
        const float* Bc = Bsm[cur];
        #pragma unroll
        for (int ks = 0; ks < 4; ks++) {
            int k0 = ks * 8 + (lane & 3);
            unsigned af[2][4], bf[8][2];
            #pragma unroll
            for (int mt = 0; mt < 2; mt++) {
                int r = wm + mt*16 + (lane >> 2);
                af[mt][0] = f2tf(Ac[r*AS_LD + k0]);
                af[mt][1] = f2tf(Ac[(r+8)*AS_LD + k0]);
                af[mt][2] = f2tf(Ac[r*AS_LD + k0 + 4]);
                af[mt][3] = f2tf(Ac[(r+8)*AS_LD + k0 + 4]);
            }
            #pragma unroll
            for (int nt = 0; nt < 8; nt++) {
                int c = wn + nt*8 + (lane >> 2);
                bf[nt][0] = f2tf(Bc[k0*BS_LD + c]);
                bf[nt][1] = f2tf(Bc[(k0+4)*BS_LD + c]);
            }
            #pragma unroll
            for (int mt = 0; mt < 2; mt++)
                #pragma unroll
                for (int nt = 0; nt < 8; nt++)
                    mma_tf32(acc[mt][nt], af[mt], bf[nt]);
        }
        __syncthreads();
    }

    // epilogue: + bias, write fp32
    #pragma unroll
    for (int nt = 0; nt < 8; nt++) {
        int c0 = bx*128 + wn + nt*8 + (lane & 3)*2;
        float bv0 = bias[c0], bv1 = bias[c0 + 1];
        #pragma unroll
        for (int mt = 0; mt < 2; mt++) {
            int r0 = by*128 + wm + mt*16 + (lane >> 2);
            float2 v0 = { acc[mt][nt][0] + bv0, acc[mt][nt][1] + bv1 };
            float2 v1 = { acc[mt][nt][2] + bv0, acc[mt][nt][3] + bv1 };
            *(float2*)(C + (size_t)r0       * HDIM + c0) = v0;
            *(float2*)(C + (size_t)(r0 + 8) * HDIM + c0) = v1;
        }
    }
}

// ---- block reduction over 256 threads ----
__device__ __forceinline__ float blockSum256(float v) {
    #pragma unroll
    for (int o = 16; o > 0; o >>= 1) v += __shfl_xor_sync(0xffffffffu, v, o);
    __shared__ float sh[8];
    int w = threadIdx.x >> 5, l = threadIdx.x & 31;
    if (l == 0) sh[w] = v;
    __syncthreads();
    if (w == 0) {
        float x = (l < 8) ? sh[l] : 0.f;
        #pragma unroll
        for (int o = 4; o > 0; o >>= 1) x += __shfl_xor_sync(0xffffffffu, x, o);
        if (l == 0) sh[0] = x;
    }
    __syncthreads();
    float r = sh[0];
    __syncthreads();
    return r;
}

// ---- in-place LayerNorm + ReLU over rows of 1024 ----
__global__ void __launch_bounds__(256) k_ln_relu(
    float* __restrict__ buf, const float* __restrict__ gamma, const float* __restrict__ beta)
{
    const int row = blockIdx.x;
    float* x = buf + (size_t)row * HDIM;
    const int t = threadIdx.x;
    float4 v = *(const float4*)(x + t*4);
    float s  = blockSum256(v.x + v.y + v.z + v.w);
    float mu = s * (1.f / HDIM);
    float d0 = v.x-mu, d1 = v.y-mu, d2 = v.z-mu, d3 = v.w-mu;
    float sq = blockSum256(d0*d0 + d1*d1 + d2*d2 + d3*d3);
    float inv = rsqrtf(sq * (1.f / HDIM) + 1e-5f);
    float4 g = *(const float4*)(gamma + t*4);
    float4 b = *(const float4*)(beta  + t*4);
    float4 o;
    o.x = fmaxf(d0*inv*g.x + b.x, 0.f);
    o.y = fmaxf(d1*inv*g.y + b.y, 0.f);
    o.z = fmaxf(d2*inv*g.z + b.z, 0.f);
    o.w = fmaxf(d3*inv*g.w + b.w, 0.f);
    *(float4*)(x + t*4) = o;
}

// ---- final: LN+ReLU(hid) -> dot Wg2 -> sigmoid gates -> gate ner/top, write out ----
__global__ void __launch_bounds__(256) k_gate_finish(
    const float* __restrict__ gg, const float* __restrict__ bgv,
    const float* __restrict__ Wg2, const float* __restrict__ bg2,
    float* __restrict__ out)
{
    const int row  = blockIdx.x;
    const int lang = d_lang[row / SEQ];
    const int t    = threadIdx.x;
    const float* x = d_hid + (size_t)row * HDIM;
    float4 v = *(const float4*)(x + t*4);
    float s  = blockSum256(v.x + v.y + v.z + v.w);
    float mu = s * (1.f / HDIM);
    float d0 = v.x-mu, d1 = v.y-mu, d2 = v.z-mu, d3 = v.w-mu;
    float sq = blockSum256(d0*d0 + d1*d1 + d2*d2 + d3*d3);
    float inv = rsqrtf(sq * (1.f / HDIM) + 1e-5f);
    float4 g = *(const float4*)(gg  + (size_t)lang*HDIM + t*4);
    float4 b = *(const float4*)(bgv + (size_t)lang*HDIM + t*4);
    float h0 = fmaxf(d0*inv*g.x + b.x, 0.f);
    float h1 = fmaxf(d1*inv*g.y + b.y, 0.f);
    float h2 = fmaxf(d2*inv*g.z + b.z, 0.f);
    float h3 = fmaxf(d3*inv*g.w + b.w, 0.f);
    const float* w2 = Wg2 + (size_t)lang * HDIM * 2 + (size_t)t * 8;
    float4 wa = *(const float4*)(w2);
    float4 wb = *(const float4*)(w2 + 4);
    float s0 = h0*wa.x + h1*wa.z + h2*wb.x + h3*wb.z;
    float s1 = h0*wa.y + h1*wa.w + h2*wb.y + h3*wb.w;
    s0 = blockSum256(s0);
    s1 = blockSum256(s1);
    float g0 = 1.f / (1.f + expf(-(s0 + bg2[lang*2 + 0])));
    float g1 = 1.f / (1.f + expf(-(s1 + bg2[lang*2 + 1])));
    size_t off = (size_t)row * HDIM + (size_t)t * 4;
    float4 nv = *(const float4*)(d_nerT + off);
    float4 tv = *(const float4*)(d_topT + off);
    float4 on = {nv.x*g0, nv.y*g0, nv.z*g0, nv.w*g0};
    float4 ot = {tv.x*g1, tv.y*g1, tv.z*g1, tv.w*g1};
    *(float4*)(out + off) = on;
    *(float4*)(out + (size_t)MTOK*HDIM + off) = ot;
}

extern "C" void kernel_launch(void* const* d_in, const int* in_sizes, int n_in,
                              void* d_out, int out_size)
{
    const float* ner    = (const float*)d_in[0];
    const float* topf   = (const float*)d_in[1];
    const int*   lang   = (const int*)d_in[2];
    const float* W_ner  = (const float*)d_in[3];
    const float* b_ner  = (const float*)d_in[4];
    const float* g_ner  = (const float*)d_in[5];
    const float* be_ner = (const float*)d_in[6];
    const float* W_top  = (const float*)d_in[7];
    const float* b_top  = (const float*)d_in[8];
    const float* g_top  = (const float*)d_in[9];
    const float* be_top = (const float*)d_in[10];
    const float* Wg1    = (const float*)d_in[11];
    const float* bg1    = (const float*)d_in[12];
    const float* gg     = (const float*)d_in[13];
    const float* bg     = (const float*)d_in[14];
    const float* Wg2    = (const float*)d_in[15];
    const float* bg2    = (const float*)d_in[16];
    float* out = (float*)d_out;

    float *pNer = nullptr, *pTop = nullptr, *pHid = nullptr;
    cudaGetSymbolAddress((void**)&pNer, d_nerT);
    cudaGetSymbolAddress((void**)&pTop, d_topT);
    cudaGetSymbolAddress((void**)&pHid, d_hid);

    static bool attr_done = false;
    if (!attr_done) {
        cudaFuncSetAttribute(k_mm_tf32<false>, cudaFuncAttributeMaxDynamicSharedMemorySize, SMEM_BYTES);
        cudaFuncSetAttribute(k_mm_tf32<true>,  cudaFuncAttributeMaxDynamicSharedMemorySize, SMEM_BYTES);
        attr_done = true;
    }

    k_decode_lang<<<1, 32>>>(lang);

    dim3 grid(HDIM/128, MTOK/128);  // (8, 64)
    k_mm_tf32<false><<<grid, 256, SMEM_BYTES>>>(ner,  W_ner, b_ner, pNer, EDIM);
    k_mm_tf32<false><<<grid, 256, SMEM_BYTES>>>(topf, W_top, b_top, pTop, EDIM);

    k_ln_relu<<<MTOK, 256>>>(pNer, g_ner, be_ner);
    k_ln_relu<<<MTOK, 256>>>(pTop, g_top, be_top);

    k_mm_tf32<true><<<grid, 256, SMEM_BYTES>>>(nullptr, Wg1, bg1, pHid, 2*HDIM);

    k_gate_finish<<<MTOK, 256>>>(gg, bg, Wg2, bg2, out);
}

// round 4
// speedup vs baseline: 4.9969x; 1.9826x over previous
#include <cuda_runtime.h>
#include <cuda_fp16.h>
#include <cstdint>

#define NB    16
#define SEQ   512
#define MTOK  8192
#define EDIM  768
#define HDIM  1024
#define NLANG 5

// ---------------- scratch (static device globals; allocation-free) ----------------
__device__ __align__(128) __half d_nerH [MTOK*EDIM];        // fp16 features
__device__ __align__(128) __half d_topH [MTOK*EDIM];
__device__ __align__(128) __half d_WtNerH[HDIM*EDIM];       // W^T [n][k] fp16
__device__ __align__(128) __half d_WtTopH[HDIM*EDIM];
__device__ __align__(128) __half d_Wg1tH[NLANG*HDIM*2*HDIM];// Wg1^T [l][n][k] fp16
__device__ __align__(128) __half d_actH [MTOK*2*HDIM];      // [ner | top] LN'd fp16
__device__ float d_nerT[MTOK*HDIM];                          // fp32 LN'd transforms
__device__ float d_topT[MTOK*HDIM];
__device__ float d_hid [MTOK*HDIM];
__device__ int   d_lang[NB];

// ---------------- PTX helpers ----------------
__device__ __forceinline__ uint32_t smem_u32(const void* p) {
    uint32_t a;
    asm("{ .reg .u64 t; cvta.to.shared.u64 t, %1; cvt.u32.u64 %0, t; }" : "=r"(a) : "l"(p));
    return a;
}
#define CP16(dst, src) asm volatile("cp.async.cg.shared.global [%0], [%1], 16;\n"::"r"(dst),"l"(src))
#define CP_COMMIT()    asm volatile("cp.async.commit_group;\n")
#define CP_WAIT(n)     asm volatile("cp.async.wait_group %0;\n"::"n"(n))

#define LDSM4(r, a) \
    asm volatile("ldmatrix.sync.aligned.m8n8.x4.shared.b16 {%0,%1,%2,%3}, [%4];" \
        : "=r"((r)[0]), "=r"((r)[1]), "=r"((r)[2]), "=r"((r)[3]) : "r"(a))

#define MMA16816(d, a, b) \
    asm volatile("mma.sync.aligned.m16n8k16.row.col.f32.f16.f16.f32 " \
        "{%0,%1,%2,%3}, {%4,%5,%6,%7}, {%8,%9}, {%0,%1,%2,%3};" \
        : "+f"((d)[0]), "+f"((d)[1]), "+f"((d)[2]), "+f"((d)[3]) \
        : "r"((a)[0]), "r"((a)[1]), "r"((a)[2]), "r"((a)[3]), "r"((b)[0]), "r"((b)[1]))

// smem: pitch 40 halfs (80 B) -> ldmatrix bank-conflict-free ((5r+c) mod 8 bijective)
#define PITCH_B  80
#define TILE_BYTES (128*PITCH_B)       // 10240
#define SM_A(s)  ((s)*TILE_BYTES)
#define SM_B(s)  (2*TILE_BYTES + (s)*TILE_BYTES)
#define SMEM_MM  (4*TILE_BYTES)        // 40960

// ---------------- decode language ids (int32 or int64 storage) ----------------
__global__ void k_decode_lang(const int* __restrict__ lp) {
    if (threadIdx.x == 0 && blockIdx.x == 0) {
        int m = 0;
        #pragma unroll
        for (int i = 1; i < 16; i += 2) m |= lp[i];
        bool is64 = (m == 0);
        for (int b = 0; b < NB; b++) d_lang[b] = is64 ? lp[2*b] : lp[b];
    }
}

// ---------------- convert features fp32 -> fp16 ----------------
__global__ void k_cvt_feat(const float* __restrict__ a, const float* __restrict__ b, int n4) {
    int i = blockIdx.x * blockDim.x + threadIdx.x;
    if (i >= n4) return;
    float4 va = ((const float4*)a)[i];
    float4 vb = ((const float4*)b)[i];
    ((__half2*)d_nerH)[2*i]   = __floats2half2_rn(va.x, va.y);
    ((__half2*)d_nerH)[2*i+1] = __floats2half2_rn(va.z, va.w);
    ((__half2*)d_topH)[2*i]   = __floats2half2_rn(vb.x, vb.y);
    ((__half2*)d_topH)[2*i+1] = __floats2half2_rn(vb.z, vb.w);
}

// ---------------- transpose + convert: src fp32 [K][N] -> dst fp16 [N][K] ----------------
__global__ void k_transpose_cvt(const float* __restrict__ src, __half* __restrict__ dst, int K, int N) {
    __shared__ float t[32][33];
    int k0 = blockIdx.y * 32, n0 = blockIdx.x * 32, z = blockIdx.z;
    src += (size_t)z * K * N;
    dst += (size_t)z * N * K;
    #pragma unroll
    for (int i = threadIdx.y; i < 32; i += 8)
        t[i][threadIdx.x] = src[(size_t)(k0 + i) * N + n0 + threadIdx.x];
    __syncthreads();
    #pragma unroll
    for (int i = threadIdx.y; i < 32; i += 8)
        dst[(size_t)(n0 + i) * K + k0 + threadIdx.x] = __float2half_rn(t[threadIdx.x][i]);
}

// ---------------- fp16 tensor-core GEMM: C[128,128] tile = A[m][k] @ Wt[n][k]^T + bias ----
// GATE: A = d_actH (K=2048), W/bias per-language. Else blockIdx.z picks ner/top.
template<int NK, bool GATE>
__global__ void __launch_bounds__(256, 2) k_mm_fp16(
    const __half* __restrict__ A0, const __half* __restrict__ A1,
    const __half* __restrict__ W0, const __half* __restrict__ W1,
    const float* __restrict__ bz0, const float* __restrict__ bz1,
    float* __restrict__ C0, float* __restrict__ C1)
{
    constexpr int K = NK * 32;
    extern __shared__ __align__(128) char smem[];
    const uint32_t sb = smem_u32(smem);
    const int tid = threadIdx.x, wid = tid >> 5, l = tid & 31;
    const int m0 = blockIdx.y * 128, n0 = blockIdx.x * 128;
    const int wm = (wid & 1) * 64, wn = (wid >> 1) * 32;

    const __half *Ah, *Wt; const float *bias; float *C;
    if (GATE) {
        int lang = d_lang[blockIdx.y >> 2];
        Ah = A0;
        Wt = W0 + (size_t)lang * HDIM * (2*HDIM);
        bias = bz0 + lang * HDIM;
        C = C0;
    } else {
        bool z = (blockIdx.z != 0);
        Ah = z ? A1 : A0; Wt = z ? W1 : W0; bias = z ? bz1 : bz0; C = z ? C1 : C0;
    }

    // per-lane ldmatrix address parts
    const uint32_t laneA = (uint32_t)((l & 15) * PITCH_B + (l >> 4) * 16);
    const uint32_t laneB = (uint32_t)(((l & 7) + ((l >> 4) << 3)) * PITCH_B + ((l >> 3) & 1) * 16);

    auto loadT = [&](int it, int stage) {
        const int kc = it * 32;
        const uint32_t aB = sb + SM_A(stage);
        const uint32_t bB = sb + SM_B(stage);
        #pragma unroll
        for (int i = 0; i < 2; i++) {
            int idx = tid + i * 256;
            int r = idx >> 2, c = idx & 3;
            CP16(aB + r * PITCH_B + c * 16, Ah + (size_t)(m0 + r) * K + kc + c * 8);
            CP16(bB + r * PITCH_B + c * 16, Wt + (size_t)(n0 + r) * K + kc + c * 8);
        }
    };

    float acc[4][4][4] = {};

    loadT(0, 0);
    CP_COMMIT();
    for (int it = 0; it < NK; it++) {
        const int cur = it & 1;
        if (it + 1 < NK) {
            loadT(it + 1, cur ^ 1);
            CP_COMMIT();
            CP_WAIT(1);
        } else {
            CP_WAIT(0);
        }
        __syncthreads();
        const uint32_t aBase = sb + SM_A(cur) + (uint32_t)(wm * PITCH_B) + laneA;
        const uint32_t bBase = sb + SM_B(cur) + (uint32_t)(wn * PITCH_B) + laneB;
        #pragma unroll
        for (int ks = 0; ks < 2; ks++) {
            uint32_t af[4][4], bf[4][2];
            #pragma unroll
            for (int mt = 0; mt < 4; mt++)
                LDSM4(af[mt], aBase + mt * (16 * PITCH_B) + ks * 32);
            #pragma unroll
            for (int nb = 0; nb < 2; nb++) {
                uint32_t t4[4];
                LDSM4(t4, bBase + nb * (16 * PITCH_B) + ks * 32);
                bf[nb*2][0] = t4[0]; bf[nb*2][1] = t4[1];
                bf[nb*2+1][0] = t4[2]; bf[nb*2+1][1] = t4[3];
            }
            #pragma unroll
            for (int mt = 0; mt < 4; mt++)
                #pragma unroll
                for (int nt = 0; nt < 4; nt++)
                    MMA16816(acc[mt][nt], af[mt], bf[nt]);
        }
        __syncthreads();
    }

    // epilogue: + bias (fp32), store fp32
    #pragma unroll
    for (int mt = 0; mt < 4; mt++) {
        int r0 = m0 + wm + mt * 16 + (l >> 2);
        #pragma unroll
        for (int nt = 0; nt < 4; nt++) {
            int c = n0 + wn + nt * 8 + 2 * (l & 3);
            float bv0 = bias[c], bv1 = bias[c + 1];
            float2 v0 = { acc[mt][nt][0] + bv0, acc[mt][nt][1] + bv1 };
            float2 v1 = { acc[mt][nt][2] + bv0, acc[mt][nt][3] + bv1 };
            *(float2*)(C + (size_t)r0 * HDIM + c) = v0;
            *(float2*)(C + (size_t)(r0 + 8) * HDIM + c) = v1;
        }
    }
}

// ---------------- block reduction over 256 threads ----------------
__device__ __forceinline__ float blockSum256(float v) {
    #pragma unroll
    for (int o = 16; o > 0; o >>= 1) v += __shfl_xor_sync(0xffffffffu, v, o);
    __shared__ float sh[8];
    int w = threadIdx.x >> 5, l = threadIdx.x & 31;
    if (l == 0) sh[w] = v;
    __syncthreads();
    if (w == 0) {
        float x = (l < 8) ? sh[l] : 0.f;
        #pragma unroll
        for (int o = 4; o > 0; o >>= 1) x += __shfl_xor_sync(0xffffffffu, x, o);
        if (l == 0) sh[0] = x;
    }
    __syncthreads();
    float r = sh[0];
    __syncthreads();
    return r;
}

// ---------------- LN + ReLU in place (fp32) + fp16 copy into concat buffer ----------------
__global__ void __launch_bounds__(256) k_ln_relu2(
    const float* __restrict__ gN, const float* __restrict__ bN,
    const float* __restrict__ gT, const float* __restrict__ bT)
{
    int row = blockIdx.x;
    float* buf; const float* gamma; const float* beta; int hoff;
    if (row < MTOK) { buf = d_nerT; gamma = gN; beta = bN; hoff = 0; }
    else            { buf = d_topT; gamma = gT; beta = bT; hoff = HDIM; row -= MTOK; }
    float* x = buf + (size_t)row * HDIM;
    const int t = threadIdx.x;
    float4 v = *(const float4*)(x + t * 4);
    float s  = blockSum256(v.x + v.y + v.z + v.w);
    float mu = s * (1.f / HDIM);
    float d0 = v.x - mu, d1 = v.y - mu, d2 = v.z - mu, d3 = v.w - mu;
    float sq = blockSum256(d0*d0 + d1*d1 + d2*d2 + d3*d3);
    float inv = rsqrtf(sq * (1.f / HDIM) + 1e-5f);
    float4 g = *(const float4*)(gamma + t * 4);
    float4 b = *(const float4*)(beta  + t * 4);
    float4 o;
    o.x = fmaxf(d0*inv*g.x + b.x, 0.f);
    o.y = fmaxf(d1*inv*g.y + b.y, 0.f);
    o.z = fmaxf(d2*inv*g.z + b.z, 0.f);
    o.w = fmaxf(d3*inv*g.w + b.w, 0.f);
    *(float4*)(x + t * 4) = o;
    __half2* dh = (__half2*)(d_actH + (size_t)row * (2*HDIM) + hoff + t * 4);
    dh[0] = __floats2half2_rn(o.x, o.y);
    dh[1] = __floats2half2_rn(o.z, o.w);
}

// ---------------- final: LN+ReLU(hid) -> Wg2 dot -> sigmoid -> gate, write out ----------------
__global__ void __launch_bounds__(256) k_gate_finish(
    const float* __restrict__ gg, const float* __restrict__ bgv,
    const float* __restrict__ Wg2, const float* __restrict__ bg2,
    float* __restrict__ out)
{
    const int row  = blockIdx.x;
    const int lang = d_lang[row / SEQ];
    const int t    = threadIdx.x;
    const float* x = d_hid + (size_t)row * HDIM;
    float4 v = *(const float4*)(x + t * 4);
    float s  = blockSum256(v.x + v.y + v.z + v.w);
    float mu = s * (1.f / HDIM);
    float d0 = v.x - mu, d1 = v.y - mu, d2 = v.z - mu, d3 = v.w - mu;
    float sq = blockSum256(d0*d0 + d1*d1 + d2*d2 + d3*d3);
    float inv = rsqrtf(sq * (1.f / HDIM) + 1e-5f);
    float4 g = *(const float4*)(gg  + (size_t)lang * HDIM + t * 4);
    float4 b = *(const float4*)(bgv + (size_t)lang * HDIM + t * 4);
    float h0 = fmaxf(d0*inv*g.x + b.x, 0.f);
    float h1 = fmaxf(d1*inv*g.y + b.y, 0.f);
    float h2 = fmaxf(d2*inv*g.z + b.z, 0.f);
    float h3 = fmaxf(d3*inv*g.w + b.w, 0.f);
    const float* w2 = Wg2 + (size_t)lang * HDIM * 2 + (size_t)t * 8;
    float4 wa = *(const float4*)(w2);
    float4 wb = *(const float4*)(w2 + 4);
    float s0 = h0*wa.x + h1*wa.z + h2*wb.x + h3*wb.z;
    float s1 = h0*wa.y + h1*wa.w + h2*wb.y + h3*wb.w;
    s0 = blockSum256(s0);
    s1 = blockSum256(s1);
    float g0 = 1.f / (1.f + expf(-(s0 + bg2[lang*2 + 0])));
    float g1 = 1.f / (1.f + expf(-(s1 + bg2[lang*2 + 1])));
    size_t off = (size_t)row * HDIM + (size_t)t * 4;
    float4 nv = *(const float4*)(d_nerT + off);
    float4 tv = *(const float4*)(d_topT + off);
    float4 on = {nv.x*g0, nv.y*g0, nv.z*g0, nv.w*g0};
    float4 ot = {tv.x*g1, tv.y*g1, tv.z*g1, tv.w*g1};
    *(float4*)(out + off) = on;
    *(float4*)(out + (size_t)MTOK*HDIM + off) = ot;
}

extern "C" void kernel_launch(void* const* d_in, const int* in_sizes, int n_in,
                              void* d_out, int out_size)
{
    const float* ner    = (const float*)d_in[0];
    const float* topf   = (const float*)d_in[1];
    const int*   lang   = (const int*)d_in[2];
    const float* W_ner  = (const float*)d_in[3];
    const float* b_ner  = (const float*)d_in[4];
    const float* g_ner  = (const float*)d_in[5];
    const float* be_ner = (const float*)d_in[6];
    const float* W_top  = (const float*)d_in[7];
    const float* b_top  = (const float*)d_in[8];
    const float* g_top  = (const float*)d_in[9];
    const float* be_top = (const float*)d_in[10];
    const float* Wg1    = (const float*)d_in[11];
    const float* bg1    = (const float*)d_in[12];
    const float* gg     = (const float*)d_in[13];
    const float* bg     = (const float*)d_in[14];
    const float* Wg2    = (const float*)d_in[15];
    const float* bg2    = (const float*)d_in[16];
    float* out = (float*)d_out;

    __half *pNerH, *pTopH, *pWtNer, *pWtTop, *pWg1t, *pActH;
    float *pNerT, *pTopT, *pHid;
    cudaGetSymbolAddress((void**)&pNerH,  d_nerH);
    cudaGetSymbolAddress((void**)&pTopH,  d_topH);
    cudaGetSymbolAddress((void**)&pWtNer, d_WtNerH);
    cudaGetSymbolAddress((void**)&pWtTop, d_WtTopH);
    cudaGetSymbolAddress((void**)&pWg1t,  d_Wg1tH);
    cudaGetSymbolAddress((void**)&pActH,  d_actH);
    cudaGetSymbolAddress((void**)&pNerT,  d_nerT);
    cudaGetSymbolAddress((void**)&pTopT,  d_topT);
    cudaGetSymbolAddress((void**)&pHid,   d_hid);

    k_decode_lang<<<1, 32>>>(lang);

    const int n4 = MTOK * EDIM / 4;
    k_cvt_feat<<<(n4 + 255) / 256, 256>>>(ner, topf, n4);

    dim3 tb(32, 8);
    k_transpose_cvt<<<dim3(HDIM/32, EDIM/32, 1), tb>>>(W_ner, pWtNer, EDIM, HDIM);
    k_transpose_cvt<<<dim3(HDIM/32, EDIM/32, 1), tb>>>(W_top, pWtTop, EDIM, HDIM);
    k_transpose_cvt<<<dim3(HDIM/32, 2*HDIM/32, NLANG), tb>>>(Wg1, pWg1t, 2*HDIM, HDIM);

    // shared transforms: both GEMMs in one launch (z = 0:ner, 1:topic)
    k_mm_fp16<24,false><<<dim3(HDIM/128, MTOK/128, 2), 256, SMEM_MM>>>(
        pNerH, pTopH, pWtNer, pWtTop, b_ner, b_top, pNerT, pTopT);

    k_ln_relu2<<<2*MTOK, 256>>>(g_ner, be_ner, g_top, be_top);

    // gate MLP (K=2048), per-batch language selected
    k_mm_fp16<64,true><<<dim3(HDIM/128, MTOK/128, 1), 256, SMEM_MM>>>(
        pActH, nullptr, pWg1t, nullptr, bg1, nullptr, pHid, nullptr);

    k_gate_finish<<<MTOK, 256>>>(gg, bg, Wg2, bg2, out);
}

// round 6
// speedup vs baseline: 5.4376x; 1.0882x over previous
#include <cuda_runtime.h>
#include <cuda_fp16.h>
#include <cstdint>

#define NB    16
#define SEQ   512
#define MTOK  8192
#define EDIM  768
#define HDIM  1024
#define NLANG 5

// ---------------- scratch (static device globals; allocation-free) ----------------
__device__ __align__(128) __half d_nerH [MTOK*EDIM];          // fp16 features [m][k]
__device__ __align__(128) __half d_topH [MTOK*EDIM];
__device__ __align__(128) __half d_WnerH[EDIM*HDIM];          // W fp16, native [k][n]
__device__ __align__(128) __half d_WtopH[EDIM*HDIM];
__device__ __align__(128) __half d_Wg1H [NLANG*2*HDIM*HDIM];  // Wg1 fp16 [l][k=2H][n=H]
__device__ __align__(128) __half d_actH [MTOK*2*HDIM];        // [ner | top] LN'd fp16
__device__ float d_nerT[MTOK*HDIM];
__device__ float d_topT[MTOK*HDIM];
__device__ float d_hid [MTOK*HDIM];
__device__ int   d_lang[NB];

// ---------------- PTX helpers ----------------
__device__ __forceinline__ uint32_t smem_u32(const void* p) {
    uint32_t a;
    asm("{ .reg .u64 t; cvta.to.shared.u64 t, %1; cvt.u32.u64 %0, t; }" : "=r"(a) : "l"(p));
    return a;
}
#define CP16(dst, src) asm volatile("cp.async.cg.shared.global [%0], [%1], 16;\n"::"r"(dst),"l"(src))
#define CP_COMMIT()    asm volatile("cp.async.commit_group;\n")
#define CP_WAIT(n)     asm volatile("cp.async.wait_group %0;\n"::"n"(n))

#define LDSM4(r, a) \
    asm volatile("ldmatrix.sync.aligned.m8n8.x4.shared.b16 {%0,%1,%2,%3}, [%4];" \
        : "=r"((r)[0]), "=r"((r)[1]), "=r"((r)[2]), "=r"((r)[3]) : "r"(a))
#define LDSM4T(r, a) \
    asm volatile("ldmatrix.sync.aligned.m8n8.x4.trans.shared.b16 {%0,%1,%2,%3}, [%4];" \
        : "=r"((r)[0]), "=r"((r)[1]), "=r"((r)[2]), "=r"((r)[3]) : "r"(a))

#define MMA16816(d, a, b) \
    asm volatile("mma.sync.aligned.m16n8k16.row.col.f32.f16.f16.f32 " \
        "{%0,%1,%2,%3}, {%4,%5,%6,%7}, {%8,%9}, {%0,%1,%2,%3};" \
        : "+f"((d)[0]), "+f"((d)[1]), "+f"((d)[2]), "+f"((d)[3]) \
        : "r"((a)[0]), "r"((a)[1]), "r"((a)[2]), "r"((a)[3]), "r"((b)[0]), "r"((b)[1]))

// smem tiles (bytes): A [128 m][72 halfs] pitch 144B ((9r+c)%8 bijective);
//                     B [64 k][264 halfs] pitch 528B ((33r+c)%8 bijective)
#define APITCH   144
#define BPITCH   528
#define A_TILE   (128*APITCH)              // 18432
#define B_TILE   (64*BPITCH)               // 33792
#define STAGE    (A_TILE + B_TILE)         // 52224
#define SM_A(s)  ((s)*STAGE)
#define SM_B(s)  ((s)*STAGE + A_TILE)
#define SMEM_MM  (2*STAGE)                 // 104448

// ---------------- fused prep: fp32 -> fp16 for all operands + lang decode ----------------
#define R_FEAT  (MTOK*EDIM/4)
#define R_WSH   (EDIM*HDIM/4)
#define R_WG1   (NLANG*2*HDIM*HDIM/4)
#define R_TOTAL (2*R_FEAT + 2*R_WSH + R_WG1)
__global__ void __launch_bounds__(256) k_prep(
    const float* __restrict__ ner, const float* __restrict__ topf,
    const float* __restrict__ Wner, const float* __restrict__ Wtop,
    const float* __restrict__ Wg1, const int* __restrict__ lp)
{
    int i = blockIdx.x * blockDim.x + threadIdx.x;
    if (i == 0) {
        int m = 0;
        #pragma unroll
        for (int j = 1; j < 16; j += 2) m |= lp[j];
        bool is64 = (m == 0);
        for (int b = 0; b < NB; b++) d_lang[b] = is64 ? lp[2*b] : lp[b];
    }
    const float* src; __half* dst; int off;
    if      (i < R_FEAT)                 { src = ner;  dst = d_nerH;  off = i; }
    else if (i < 2*R_FEAT)               { src = topf; dst = d_topH;  off = i - R_FEAT; }
    else if (i < 2*R_FEAT + R_WSH)       { src = Wner; dst = d_WnerH; off = i - 2*R_FEAT; }
    else if (i < 2*R_FEAT + 2*R_WSH)     { src = Wtop; dst = d_WtopH; off = i - 2*R_FEAT - R_WSH; }
    else                                 { src = Wg1;  dst = d_Wg1H;  off = i - 2*R_FEAT - 2*R_WSH; }
    float4 v = ((const float4*)src)[off];
    __half2* d2 = (__half2*)(dst + (size_t)off * 4);
    d2[0] = __floats2half2_rn(v.x, v.y);
    d2[1] = __floats2half2_rn(v.z, v.w);
}

// ---------------- fp16 GEMM: C[128 m, 256 n] tile, A[m][k] fp16, W[k][n] fp16 (native) ---
// warp tile 32x64; B fragments via ldmatrix.trans (no weight transpose needed).
template<int NK, bool GATE>
__global__ void __launch_bounds__(512) k_mm_fp16(
    const __half* __restrict__ A0, const __half* __restrict__ A1,
    const __half* __restrict__ W0, const __half* __restrict__ W1,
    const float* __restrict__ bz0, const float* __restrict__ bz1,
    float* __restrict__ C0, float* __restrict__ C1)
{
    constexpr int K = NK * 64;
    extern __shared__ __align__(128) char smem[];
    const uint32_t sb = smem_u32(smem);
    const int tid = threadIdx.x, wid = tid >> 5, l = tid & 31;
    const int m0 = blockIdx.y * 128, n0 = blockIdx.x * 256;
    const int wm = (wid & 3) * 32, wn = (wid >> 2) * 64;

    const __half *Ah, *Wt; const float *bias; float *C;
    if (GATE) {
        int lang = d_lang[blockIdx.y >> 2];
        Ah = A0;
        Wt = W0 + (size_t)lang * (2*HDIM) * HDIM;
        bias = bz0 + lang * HDIM;
        C = C0;
    } else {
        bool z = (blockIdx.z != 0);
        Ah = z ? A1 : A0; Wt = z ? W1 : W0; bias = z ? bz1 : bz0; C = z ? C1 : C0;
    }

    const uint32_t laneA = (uint32_t)((l & 15) * APITCH + (l >> 4) * 16);
    const uint32_t laneB = (uint32_t)((l & 15) * BPITCH + (l >> 4) * 16);

    auto loadT = [&](int it, int stage) {
        const int kc = it * 64;
        const uint32_t aB = sb + SM_A(stage);
        const uint32_t bB = sb + SM_B(stage);
        #pragma unroll
        for (int i = 0; i < 2; i++) {          // A: 128 rows x 8 x 16B
            int idx = tid + i * 512;
            int r = idx >> 3, c = idx & 7;
            CP16(aB + r * APITCH + c * 16, Ah + (size_t)(m0 + r) * K + kc + c * 8);
        }
        #pragma unroll
        for (int i = 0; i < 4; i++) {          // B: 64 rows x 32 x 16B
            int idx = tid + i * 512;
            int r = idx >> 5, c = idx & 31;
            CP16(bB + r * BPITCH + c * 16, Wt + (size_t)(kc + r) * HDIM + n0 + c * 8);
        }
    };

    float acc[2][8][4] = {};

    loadT(0, 0);
    CP_COMMIT();
    for (int it = 0; it < NK; it++) {
        const int cur = it & 1;
        if (it + 1 < NK) {
            loadT(it + 1, cur ^ 1);            // fill other stage
            CP_COMMIT();
            CP_WAIT(1);                        // my copies for stage cur done
        } else {
            CP_WAIT(0);
        }
        __syncthreads();                       // ALL threads' stage-cur copies visible
        const uint32_t aBase = sb + SM_A(cur) + (uint32_t)(wm * APITCH) + laneA;
        const uint32_t bBase = sb + SM_B(cur) + (uint32_t)(wn * 2) + laneB;
        #pragma unroll
        for (int ks = 0; ks < 4; ks++) {
            uint32_t af[2][4], bf[8][2];
            #pragma unroll
            for (int mt = 0; mt < 2; mt++)
                LDSM4(af[mt], aBase + mt * (16 * APITCH) + ks * 32);
            #pragma unroll
            for (int j = 0; j < 4; j++) {
                uint32_t t4[4];
                LDSM4T(t4, bBase + ks * (16 * BPITCH) + j * 32);
                bf[2*j][0] = t4[0]; bf[2*j][1] = t4[1];
                bf[2*j+1][0] = t4[2]; bf[2*j+1][1] = t4[3];
            }
            #pragma unroll
            for (int mt = 0; mt < 2; mt++)
                #pragma unroll
                for (int nt = 0; nt < 8; nt++)
                    MMA16816(acc[mt][nt], af[mt], bf[nt]);
        }
        __syncthreads();                       // reads done before next overwrite
    }

    // epilogue: + bias (fp32), store fp32
    #pragma unroll
    for (int mt = 0; mt < 2; mt++) {
        int r0 = m0 + wm + mt * 16 + (l >> 2);
        #pragma unroll
        for (int nt = 0; nt < 8; nt++) {
            int c = n0 + wn + nt * 8 + 2 * (l & 3);
            float bv0 = bias[c], bv1 = bias[c + 1];
            float2 v0 = { acc[mt][nt][0] + bv0, acc[mt][nt][1] + bv1 };
            float2 v1 = { acc[mt][nt][2] + bv0, acc[mt][nt][3] + bv1 };
            *(float2*)(C + (size_t)r0 * HDIM + c) = v0;
            *(float2*)(C + (size_t)(r0 + 8) * HDIM + c) = v1;
        }
    }
}

// ---------------- block reduction over 256 threads ----------------
__device__ __forceinline__ float blockSum256(float v) {
    #pragma unroll
    for (int o = 16; o > 0; o >>= 1) v += __shfl_xor_sync(0xffffffffu, v, o);
    __shared__ float sh[8];
    int w = threadIdx.x >> 5, l = threadIdx.x & 31;
    if (l == 0) sh[w] = v;
    __syncthreads();
    if (w == 0) {
        float x = (l < 8) ? sh[l] : 0.f;
        #pragma unroll
        for (int o = 4; o > 0; o >>= 1) x += __shfl_xor_sync(0xffffffffu, x, o);
        if (l == 0) sh[0] = x;
    }
    __syncthreads();
    float r = sh[0];
    __syncthreads();
    return r;
}

// ---------------- LN + ReLU in place (fp32) + fp16 copy into concat buffer ----------------
__global__ void __launch_bounds__(256) k_ln_relu2(
    const float* __restrict__ gN, const float* __restrict__ bN,
    const float* __restrict__ gT, const float* __restrict__ bT)
{
    int row = blockIdx.x;
    float* buf; const float* gamma; const float* beta; int hoff;
    if (row < MTOK) { buf = d_nerT; gamma = gN; beta = bN; hoff = 0; }
    else            { buf = d_topT; gamma = gT; beta = bT; hoff = HDIM; row -= MTOK; }
    float* x = buf + (size_t)row * HDIM;
    const int t = threadIdx.x;
    float4 v = *(const float4*)(x + t * 4);
    float s  = blockSum256(v.x + v.y + v.z + v.w);
    float mu = s * (1.f / HDIM);
    float d0 = v.x - mu, d1 = v.y - mu, d2 = v.z - mu, d3 = v.w - mu;
    float sq = blockSum256(d0*d0 + d1*d1 + d2*d2 + d3*d3);
    float inv = rsqrtf(sq * (1.f / HDIM) + 1e-5f);
    float4 g = *(const float4*)(gamma + t * 4);
    float4 b = *(const float4*)(beta  + t * 4);
    float4 o;
    o.x = fmaxf(d0*inv*g.x + b.x, 0.f);
    o.y = fmaxf(d1*inv*g.y + b.y, 0.f);
    o.z = fmaxf(d2*inv*g.z + b.z, 0.f);
    o.w = fmaxf(d3*inv*g.w + b.w, 0.f);
    *(float4*)(x + t * 4) = o;
    __half2* dh = (__half2*)(d_actH + (size_t)row * (2*HDIM) + hoff + t * 4);
    dh[0] = __floats2half2_rn(o.x, o.y);
    dh[1] = __floats2half2_rn(o.z, o.w);
}

// ---------------- final: LN+ReLU(hid) -> Wg2 dot -> sigmoid -> gate, write out ----------------
__global__ void __launch_bounds__(256) k_gate_finish(
    const float* __restrict__ gg, const float* __restrict__ bgv,
    const float* __restrict__ Wg2, const float* __restrict__ bg2,
    float* __restrict__ out)
{
    const int row  = blockIdx.x;
    const int lang = d_lang[row / SEQ];
    const int t    = threadIdx.x;
    const float* x = d_hid + (size_t)row * HDIM;
    float4 v = *(const float4*)(x + t * 4);
    float s  = blockSum256(v.x + v.y + v.z + v.w);
    float mu = s * (1.f / HDIM);
    float d0 = v.x - mu, d1 = v.y - mu, d2 = v.z - mu, d3 = v.w - mu;
    float sq = blockSum256(d0*d0 + d1*d1 + d2*d2 + d3*d3);
    float inv = rsqrtf(sq * (1.f / HDIM) + 1e-5f);
    float4 g = *(const float4*)(gg  + (size_t)lang * HDIM + t * 4);
    float4 b = *(const float4*)(bgv + (size_t)lang * HDIM + t * 4);
    float h0 = fmaxf(d0*inv*g.x + b.x, 0.f);
    float h1 = fmaxf(d1*inv*g.y + b.y, 0.f);
    float h2 = fmaxf(d2*inv*g.z + b.z, 0.f);
    float h3 = fmaxf(d3*inv*g.w + b.w, 0.f);
    const float* w2 = Wg2 + (size_t)lang * HDIM * 2 + (size_t)t * 8;
    float4 wa = *(const float4*)(w2);
    float4 wb = *(const float4*)(w2 + 4);
    float s0 = h0*wa.x + h1*wa.z + h2*wb.x + h3*wb.z;
    float s1 = h0*wa.y + h1*wa.w + h2*wb.y + h3*wb.w;
    s0 = blockSum256(s0);
    s1 = blockSum256(s1);
    float g0 = 1.f / (1.f + expf(-(s0 + bg2[lang*2 + 0])));
    float g1 = 1.f / (1.f + expf(-(s1 + bg2[lang*2 + 1])));
    size_t off = (size_t)row * HDIM + (size_t)t * 4;
    float4 nv = *(const float4*)(d_nerT + off);
    float4 tv = *(const float4*)(d_topT + off);
    float4 on = {nv.x*g0, nv.y*g0, nv.z*g0, nv.w*g0};
    float4 ot = {tv.x*g1, tv.y*g1, tv.z*g1, tv.w*g1};
    *(float4*)(out + off) = on;
    *(float4*)(out + (size_t)MTOK*HDIM + off) = ot;
}

extern "C" void kernel_launch(void* const* d_in, const int* in_sizes, int n_in,
                              void* d_out, int out_size)
{
    const float* ner    = (const float*)d_in[0];
    const float* topf   = (const float*)d_in[1];
    const int*   lang   = (const int*)d_in[2];
    const float* W_ner  = (const float*)d_in[3];
    const float* b_ner  = (const float*)d_in[4];
    const float* g_ner  = (const float*)d_in[5];
    const float* be_ner = (const float*)d_in[6];
    const float* W_top  = (const float*)d_in[7];
    const float* b_top  = (const float*)d_in[8];
    const float* g_top  = (const float*)d_in[9];
    const float* be_top = (const float*)d_in[10];
    const float* Wg1    = (const float*)d_in[11];
    const float* bg1    = (const float*)d_in[12];
    const float* gg     = (const float*)d_in[13];
    const float* bg     = (const float*)d_in[14];
    const float* Wg2    = (const float*)d_in[15];
    const float* bg2    = (const float*)d_in[16];
    float* out = (float*)d_out;

    __half *pNerH, *pTopH, *pWner, *pWtop, *pWg1, *pActH;
    float *pNerT, *pTopT, *pHid;
    cudaGetSymbolAddress((void**)&pNerH, d_nerH);
    cudaGetSymbolAddress((void**)&pTopH, d_topH);
    cudaGetSymbolAddress((void**)&pWner, d_WnerH);
    cudaGetSymbolAddress((void**)&pWtop, d_WtopH);
    cudaGetSymbolAddress((void**)&pWg1,  d_Wg1H);
    cudaGetSymbolAddress((void**)&pActH, d_actH);
    cudaGetSymbolAddress((void**)&pNerT, d_nerT);
    cudaGetSymbolAddress((void**)&pTopT, d_topT);
    cudaGetSymbolAddress((void**)&pHid,  d_hid);

    static bool attr_done = false;
    if (!attr_done) {
        cudaFuncSetAttribute(k_mm_fp16<12,false>, cudaFuncAttributeMaxDynamicSharedMemorySize, SMEM_MM);
        cudaFuncSetAttribute(k_mm_fp16<32,true>,  cudaFuncAttributeMaxDynamicSharedMemorySize, SMEM_MM);
        attr_done = true;
    }

    k_prep<<<R_TOTAL/256, 256>>>(ner, topf, W_ner, W_top, Wg1, lang);

    // shared transforms: both GEMMs in one launch (z = 0:ner, 1:topic)
    k_mm_fp16<12,false><<<dim3(HDIM/256, MTOK/128, 2), 512, SMEM_MM>>>(
        pNerH, pTopH, pWner, pWtop, b_ner, b_top, pNerT, pTopT);

    k_ln_relu2<<<2*MTOK, 256>>>(g_ner, be_ner, g_top, be_top);

    // gate MLP (K=2048), per-batch language selected
    k_mm_fp16<32,true><<<dim3(HDIM/256, MTOK/128, 1), 512, SMEM_MM>>>(
        pActH, nullptr, pWg1, nullptr, bg1, nullptr, pHid, nullptr);

    k_gate_finish<<<MTOK, 256>>>(gg, bg, Wg2, bg2, out);
}

// round 7
// speedup vs baseline: 5.4769x; 1.0072x over previous
#include <cuda_runtime.h>
#include <cuda_fp16.h>
#include <cstdint>

#define NB    16
#define SEQ   512
#define MTOK  8192
#define EDIM  768
#define HDIM  1024
#define NLANG 5

// ---------------- scratch (static device globals; allocation-free) ----------------
__device__ __align__(128) __half d_nerH [MTOK*EDIM];          // fp16 features [m][k]
__device__ __align__(128) __half d_topH [MTOK*EDIM];
__device__ __align__(128) __half d_WnerH[EDIM*HDIM];          // W fp16, native [k][n]
__device__ __align__(128) __half d_WtopH[EDIM*HDIM];
__device__ __align__(128) __half d_Wg1H [NLANG*2*HDIM*HDIM];  // Wg1 fp16 [l][k=2H][n=H]
__device__ __align__(128) __half d_actH [MTOK*2*HDIM];        // [ner | top] LN'd fp16
__device__ float d_nerT[MTOK*HDIM];
__device__ float d_topT[MTOK*HDIM];
__device__ float d_hid [MTOK*HDIM];
__device__ int   d_lang[NB];

// ---------------- PTX helpers ----------------
__device__ __forceinline__ uint32_t smem_u32(const void* p) {
    uint32_t a;
    asm("{ .reg .u64 t; cvta.to.shared.u64 t, %1; cvt.u32.u64 %0, t; }" : "=r"(a) : "l"(p));
    return a;
}
#define CP16(dst, src) asm volatile("cp.async.cg.shared.global [%0], [%1], 16;\n"::"r"(dst),"l"(src))
#define CP_COMMIT()    asm volatile("cp.async.commit_group;\n")
#define CP_WAIT(n)     asm volatile("cp.async.wait_group %0;\n"::"n"(n))

#define LDSM4(r, a) \
    asm volatile("ldmatrix.sync.aligned.m8n8.x4.shared.b16 {%0,%1,%2,%3}, [%4];" \
        : "=r"((r)[0]), "=r"((r)[1]), "=r"((r)[2]), "=r"((r)[3]) : "r"(a))
#define LDSM4T(r, a) \
    asm volatile("ldmatrix.sync.aligned.m8n8.x4.trans.shared.b16 {%0,%1,%2,%3}, [%4];" \
        : "=r"((r)[0]), "=r"((r)[1]), "=r"((r)[2]), "=r"((r)[3]) : "r"(a))

#define MMA16816(d, a, b) \
    asm volatile("mma.sync.aligned.m16n8k16.row.col.f32.f16.f16.f32 " \
        "{%0,%1,%2,%3}, {%4,%5,%6,%7}, {%8,%9}, {%0,%1,%2,%3};" \
        : "+f"((d)[0]), "+f"((d)[1]), "+f"((d)[2]), "+f"((d)[3]) \
        : "r"((a)[0]), "r"((a)[1]), "r"((a)[2]), "r"((a)[3]), "r"((b)[0]), "r"((b)[1]))

// smem tiles (bytes): A [128 m][72 halfs] pitch 144B ((9r+c)%8 bijective);
//                     B [64 k][264 halfs] pitch 528B ((33r+c)%8 bijective)
#define APITCH   144
#define BPITCH   528
#define A_TILE   (128*APITCH)              // 18432
#define B_TILE   (64*BPITCH)               // 33792
#define STAGE    (A_TILE + B_TILE)         // 52224
#define NSTAGE   3
#define SM_A(s)  ((s)*STAGE)
#define SM_B(s)  ((s)*STAGE + A_TILE)
#define SMEM_MM  (NSTAGE*STAGE)            // 156672

// ---------------- fused prep: fp32 -> fp16 for all operands + lang decode ----------------
#define R_FEAT  (MTOK*EDIM/4)
#define R_WSH   (EDIM*HDIM/4)
#define R_WG1   (NLANG*2*HDIM*HDIM/4)
#define R_TOTAL (2*R_FEAT + 2*R_WSH + R_WG1)
__global__ void __launch_bounds__(256) k_prep(
    const float* __restrict__ ner, const float* __restrict__ topf,
    const float* __restrict__ Wner, const float* __restrict__ Wtop,
    const float* __restrict__ Wg1, const int* __restrict__ lp)
{
    int i = blockIdx.x * blockDim.x + threadIdx.x;
    if (i == 0) {
        int m = 0;
        #pragma unroll
        for (int j = 1; j < 16; j += 2) m |= lp[j];
        bool is64 = (m == 0);
        for (int b = 0; b < NB; b++) d_lang[b] = is64 ? lp[2*b] : lp[b];
    }
    const float* src; __half* dst; int off;
    if      (i < R_FEAT)                 { src = ner;  dst = d_nerH;  off = i; }
    else if (i < 2*R_FEAT)               { src = topf; dst = d_topH;  off = i - R_FEAT; }
    else if (i < 2*R_FEAT + R_WSH)       { src = Wner; dst = d_WnerH; off = i - 2*R_FEAT; }
    else if (i < 2*R_FEAT + 2*R_WSH)     { src = Wtop; dst = d_WtopH; off = i - 2*R_FEAT - R_WSH; }
    else                                 { src = Wg1;  dst = d_Wg1H;  off = i - 2*R_FEAT - 2*R_WSH; }
    float4 v = ((const float4*)src)[off];
    __half2* d2 = (__half2*)(dst + (size_t)off * 4);
    d2[0] = __floats2half2_rn(v.x, v.y);
    d2[1] = __floats2half2_rn(v.z, v.w);
}

// ---------------- fp16 GEMM: C[128 m, 256 n] tile, A[m][k] fp16, W[k][n] fp16 (native) ---
// 3-stage cp.async ring, ONE __syncthreads per K-iteration.
template<int NK, bool GATE>
__global__ void __launch_bounds__(512) k_mm_fp16(
    const __half* __restrict__ A0, const __half* __restrict__ A1,
    const __half* __restrict__ W0, const __half* __restrict__ W1,
    const float* __restrict__ bz0, const float* __restrict__ bz1,
    float* __restrict__ C0, float* __restrict__ C1)
{
    constexpr int K = NK * 64;
    extern __shared__ __align__(128) char smem[];
    const uint32_t sb = smem_u32(smem);
    const int tid = threadIdx.x, wid = tid >> 5, l = tid & 31;
    const int m0 = blockIdx.y * 128, n0 = blockIdx.x * 256;
    const int wm = (wid & 3) * 32, wn = (wid >> 2) * 64;

    const __half *Ah, *Wt; const float *bias; float *C;
    if (GATE) {
        int lang = d_lang[blockIdx.y >> 2];
        Ah = A0;
        Wt = W0 + (size_t)lang * (2*HDIM) * HDIM;
        bias = bz0 + lang * HDIM;
        C = C0;
    } else {
        bool z = (blockIdx.z != 0);
        Ah = z ? A1 : A0; Wt = z ? W1 : W0; bias = z ? bz1 : bz0; C = z ? C1 : C0;
    }

    const uint32_t laneA = (uint32_t)((l & 15) * APITCH + (l >> 4) * 16);
    const uint32_t laneB = (uint32_t)((l & 15) * BPITCH + (l >> 4) * 16);

    auto loadT = [&](int it, int stage) {
        const int kc = it * 64;
        const uint32_t aB = sb + SM_A(stage);
        const uint32_t bB = sb + SM_B(stage);
        #pragma unroll
        for (int i = 0; i < 2; i++) {          // A: 128 rows x 8 x 16B
            int idx = tid + i * 512;
            int r = idx >> 3, c = idx & 7;
            CP16(aB + r * APITCH + c * 16, Ah + (size_t)(m0 + r) * K + kc + c * 8);
        }
        #pragma unroll
        for (int i = 0; i < 4; i++) {          // B: 64 rows x 32 x 16B
            int idx = tid + i * 512;
            int r = idx >> 5, c = idx & 31;
            CP16(bB + r * BPITCH + c * 16, Wt + (size_t)(kc + r) * HDIM + n0 + c * 8);
        }
    };

    float acc[2][8][4] = {};

    // prologue: fill stages 0 and 1
    loadT(0, 0); CP_COMMIT();
    loadT(1, 1); CP_COMMIT();

    int stage = 0;          // == it % 3
    int nstage = 2 % NSTAGE; // stage index for it+2
    for (int it = 0; it < NK; it++) {
        CP_WAIT(1);                            // my copies for stage `it` done
        __syncthreads();                       // everyone's done; stage it-1 consumers finished
        if (it + 2 < NK) loadT(it + 2, nstage);
        CP_COMMIT();                           // (empty group OK on tail iters)

        const uint32_t aBase = sb + SM_A(stage) + (uint32_t)(wm * APITCH) + laneA;
        const uint32_t bBase = sb + SM_B(stage) + (uint32_t)(wn * 2) + laneB;
        #pragma unroll
        for (int ks = 0; ks < 4; ks++) {
            uint32_t af[2][4], bf[8][2];
            #pragma unroll
            for (int mt = 0; mt < 2; mt++)
                LDSM4(af[mt], aBase + mt * (16 * APITCH) + ks * 32);
            #pragma unroll
            for (int j = 0; j < 4; j++) {
                uint32_t t4[4];
                LDSM4T(t4, bBase + ks * (16 * BPITCH) + j * 32);
                bf[2*j][0] = t4[0]; bf[2*j][1] = t4[1];
                bf[2*j+1][0] = t4[2]; bf[2*j+1][1] = t4[3];
            }
            #pragma unroll
            for (int mt = 0; mt < 2; mt++)
                #pragma unroll
                for (int nt = 0; nt < 8; nt++)
                    MMA16816(acc[mt][nt], af[mt], bf[nt]);
        }
        stage  = (stage  + 1 == NSTAGE) ? 0 : stage + 1;
        nstage = (nstage + 1 == NSTAGE) ? 0 : nstage + 1;
    }

    // epilogue: + bias (fp32), store fp32
    #pragma unroll
    for (int mt = 0; mt < 2; mt++) {
        int r0 = m0 + wm + mt * 16 + (l >> 2);
        #pragma unroll
        for (int nt = 0; nt < 8; nt++) {
            int c = n0 + wn + nt * 8 + 2 * (l & 3);
            float bv0 = bias[c], bv1 = bias[c + 1];
            float2 v0 = { acc[mt][nt][0] + bv0, acc[mt][nt][1] + bv1 };
            float2 v1 = { acc[mt][nt][2] + bv0, acc[mt][nt][3] + bv1 };
            *(float2*)(C + (size_t)r0 * HDIM + c) = v0;
            *(float2*)(C + (size_t)(r0 + 8) * HDIM + c) = v1;
        }
    }
}

// ---------------- block reduction over 256 threads ----------------
__device__ __forceinline__ float blockSum256(float v) {
    #pragma unroll
    for (int o = 16; o > 0; o >>= 1) v += __shfl_xor_sync(0xffffffffu, v, o);
    __shared__ float sh[8];
    int w = threadIdx.x >> 5, l = threadIdx.x & 31;
    if (l == 0) sh[w] = v;
    __syncthreads();
    if (w == 0) {
        float x = (l < 8) ? sh[l] : 0.f;
        #pragma unroll
        for (int o = 4; o > 0; o >>= 1) x += __shfl_xor_sync(0xffffffffu, x, o);
        if (l == 0) sh[0] = x;
    }
    __syncthreads();
    float r = sh[0];
    __syncthreads();
    return r;
}

// ---------------- LN + ReLU in place (fp32) + fp16 copy into concat buffer ----------------
__global__ void __launch_bounds__(256) k_ln_relu2(
    const float* __restrict__ gN, const float* __restrict__ bN,
    const float* __restrict__ gT, const float* __restrict__ bT)
{
    int row = blockIdx.x;
    float* buf; const float* gamma; const float* beta; int hoff;
    if (row < MTOK) { buf = d_nerT; gamma = gN; beta = bN; hoff = 0; }
    else            { buf = d_topT; gamma = gT; beta = bT; hoff = HDIM; row -= MTOK; }
    float* x = buf + (size_t)row * HDIM;
    const int t = threadIdx.x;
    float4 v = *(const float4*)(x + t * 4);
    float s  = blockSum256(v.x + v.y + v.z + v.w);
    float mu = s * (1.f / HDIM);
    float d0 = v.x - mu, d1 = v.y - mu, d2 = v.z - mu, d3 = v.w - mu;
    float sq = blockSum256(d0*d0 + d1*d1 + d2*d2 + d3*d3);
    float inv = rsqrtf(sq * (1.f / HDIM) + 1e-5f);
    float4 g = *(const float4*)(gamma + t * 4);
    float4 b = *(const float4*)(beta  + t * 4);
    float4 o;
    o.x = fmaxf(d0*inv*g.x + b.x, 0.f);
    o.y = fmaxf(d1*inv*g.y + b.y, 0.f);
    o.z = fmaxf(d2*inv*g.z + b.z, 0.f);
    o.w = fmaxf(d3*inv*g.w + b.w, 0.f);
    *(float4*)(x + t * 4) = o;
    __half2* dh = (__half2*)(d_actH + (size_t)row * (2*HDIM) + hoff + t * 4);
    dh[0] = __floats2half2_rn(o.x, o.y);
    dh[1] = __floats2half2_rn(o.z, o.w);
}

// ---------------- final: LN+ReLU(hid) -> Wg2 dot -> sigmoid -> gate, write out ----------------
__global__ void __launch_bounds__(256) k_gate_finish(
    const float* __restrict__ gg, const float* __restrict__ bgv,
    const float* __restrict__ Wg2, const float* __restrict__ bg2,
    float* __restrict__ out)
{
    const int row  = blockIdx.x;
    const int lang = d_lang[row / SEQ];
    const int t    = threadIdx.x;
    const float* x = d_hid + (size_t)row * HDIM;
    float4 v = *(const float4*)(x + t * 4);
    float s  = blockSum256(v.x + v.y + v.z + v.w);
    float mu = s * (1.f / HDIM);
    float d0 = v.x - mu, d1 = v.y - mu, d2 = v.z - mu, d3 = v.w - mu;
    float sq = blockSum256(d0*d0 + d1*d1 + d2*d2 + d3*d3);
    float inv = rsqrtf(sq * (1.f / HDIM) + 1e-5f);
    float4 g = *(const float4*)(gg  + (size_t)lang * HDIM + t * 4);
    float4 b = *(const float4*)(bgv + (size_t)lang * HDIM + t * 4);
    float h0 = fmaxf(d0*inv*g.x + b.x, 0.f);
    float h1 = fmaxf(d1*inv*g.y + b.y, 0.f);
    float h2 = fmaxf(d2*inv*g.z + b.z, 0.f);
    float h3 = fmaxf(d3*inv*g.w + b.w, 0.f);
    const float* w2 = Wg2 + (size_t)lang * HDIM * 2 + (size_t)t * 8;
    float4 wa = *(const float4*)(w2);
    float4 wb = *(const float4*)(w2 + 4);
    float s0 = h0*wa.x + h1*wa.z + h2*wb.x + h3*wb.z;
    float s1 = h0*wa.y + h1*wa.w + h2*wb.y + h3*wb.w;
    s0 = blockSum256(s0);
    s1 = blockSum256(s1);
    float g0 = 1.f / (1.f + expf(-(s0 + bg2[lang*2 + 0])));
    float g1 = 1.f / (1.f + expf(-(s1 + bg2[lang*2 + 1])));
    size_t off = (size_t)row * HDIM + (size_t)t * 4;
    float4 nv = *(const float4*)(d_nerT + off);
    float4 tv = *(const float4*)(d_topT + off);
    float4 on = {nv.x*g0, nv.y*g0, nv.z*g0, nv.w*g0};
    float4 ot = {tv.x*g1, tv.y*g1, tv.z*g1, tv.w*g1};
    *(float4*)(out + off) = on;
    *(float4*)(out + (size_t)MTOK*HDIM + off) = ot;
}

extern "C" void kernel_launch(void* const* d_in, const int* in_sizes, int n_in,
                              void* d_out, int out_size)
{
    const float* ner    = (const float*)d_in[0];
    const float* topf   = (const float*)d_in[1];
    const int*   lang   = (const int*)d_in[2];
    const float* W_ner  = (const float*)d_in[3];
    const float* b_ner  = (const float*)d_in[4];
    const float* g_ner  = (const float*)d_in[5];
    const float* be_ner = (const float*)d_in[6];
    const float* W_top  = (const float*)d_in[7];
    const float* b_top  = (const float*)d_in[8];
    const float* g_top  = (const float*)d_in[9];
    const float* be_top = (const float*)d_in[10];
    const float* Wg1    = (const float*)d_in[11];
    const float* bg1    = (const float*)d_in[12];
    const float* gg     = (const float*)d_in[13];
    const float* bg     = (const float*)d_in[14];
    const float* Wg2    = (const float*)d_in[15];
    const float* bg2    = (const float*)d_in[16];
    float* out = (float*)d_out;

    __half *pNerH, *pTopH, *pWner, *pWtop, *pWg1, *pActH;
    float *pNerT, *pTopT, *pHid;
    cudaGetSymbolAddress((void**)&pNerH, d_nerH);
    cudaGetSymbolAddress((void**)&pTopH, d_topH);
    cudaGetSymbolAddress((void**)&pWner, d_WnerH);
    cudaGetSymbolAddress((void**)&pWtop, d_WtopH);
    cudaGetSymbolAddress((void**)&pWg1,  d_Wg1H);
    cudaGetSymbolAddress((void**)&pActH, d_actH);
    cudaGetSymbolAddress((void**)&pNerT, d_nerT);
    cudaGetSymbolAddress((void**)&pTopT, d_topT);
    cudaGetSymbolAddress((void**)&pHid,  d_hid);

    static bool attr_done = false;
    if (!attr_done) {
        cudaFuncSetAttribute(k_mm_fp16<12,false>, cudaFuncAttributeMaxDynamicSharedMemorySize, SMEM_MM);
        cudaFuncSetAttribute(k_mm_fp16<32,true>,  cudaFuncAttributeMaxDynamicSharedMemorySize, SMEM_MM);
        attr_done = true;
    }

    k_prep<<<R_TOTAL/256, 256>>>(ner, topf, W_ner, W_top, Wg1, lang);

    // shared transforms: both GEMMs in one launch (z = 0:ner, 1:topic)
    k_mm_fp16<12,false><<<dim3(HDIM/256, MTOK/128, 2), 512, SMEM_MM>>>(
        pNerH, pTopH, pWner, pWtop, b_ner, b_top, pNerT, pTopT);

    k_ln_relu2<<<2*MTOK, 256>>>(g_ner, be_ner, g_top, be_top);

    // gate MLP (K=2048), per-batch language selected
    k_mm_fp16<32,true><<<dim3(HDIM/256, MTOK/128, 1), 512, SMEM_MM>>>(
        pActH, nullptr, pWg1, nullptr, bg1, nullptr, pHid, nullptr);

    k_gate_finish<<<MTOK, 256>>>(gg, bg, Wg2, bg2, out);
}

// round 8
// speedup vs baseline: 5.5055x; 1.0052x over previous
#include <cuda_runtime.h>
#include <cuda_fp16.h>
#include <cstdint>

#define NB    16
#define SEQ   512
#define MTOK  8192
#define EDIM  768
#define HDIM  1024
#define NLANG 5

// ---------------- scratch (static device globals; allocation-free) ----------------
__device__ __align__(128) __half d_nerH [MTOK*EDIM];          // fp16 features [m][k]
__device__ __align__(128) __half d_topH [MTOK*EDIM];
__device__ __align__(128) __half d_WnerH[EDIM*HDIM];          // W fp16, native [k][n]
__device__ __align__(128) __half d_WtopH[EDIM*HDIM];
__device__ __align__(128) __half d_Wg1H [NLANG*2*HDIM*HDIM];  // Wg1 fp16 [l][k=2H][n=H]
__device__ __align__(128) __half d_actH [MTOK*2*HDIM];        // [ner | top] LN'd fp16
__device__ float d_nerT[MTOK*HDIM];
__device__ float d_topT[MTOK*HDIM];
__device__ float d_hid [MTOK*HDIM];
__device__ int   d_lang[NB];

// ---------------- PTX helpers ----------------
__device__ __forceinline__ uint32_t smem_u32(const void* p) {
    uint32_t a;
    asm("{ .reg .u64 t; cvta.to.shared.u64 t, %1; cvt.u32.u64 %0, t; }" : "=r"(a) : "l"(p));
    return a;
}
#define CP16(dst, src) asm volatile("cp.async.cg.shared.global [%0], [%1], 16;\n"::"r"(dst),"l"(src))
#define CP_COMMIT()    asm volatile("cp.async.commit_group;\n")
#define CP_WAIT(n)     asm volatile("cp.async.wait_group %0;\n"::"n"(n))

#define LDSM4(r, a) \
    asm volatile("ldmatrix.sync.aligned.m8n8.x4.shared.b16 {%0,%1,%2,%3}, [%4];" \
        : "=r"((r)[0]), "=r"((r)[1]), "=r"((r)[2]), "=r"((r)[3]) : "r"(a))
#define LDSM4T(r, a) \
    asm volatile("ldmatrix.sync.aligned.m8n8.x4.trans.shared.b16 {%0,%1,%2,%3}, [%4];" \
        : "=r"((r)[0]), "=r"((r)[1]), "=r"((r)[2]), "=r"((r)[3]) : "r"(a))

#define MMA16816(d, a, b) \
    asm volatile("mma.sync.aligned.m16n8k16.row.col.f32.f16.f16.f32 " \
        "{%0,%1,%2,%3}, {%4,%5,%6,%7}, {%8,%9}, {%0,%1,%2,%3};" \
        : "+f"((d)[0]), "+f"((d)[1]), "+f"((d)[2]), "+f"((d)[3]) \
        : "r"((a)[0]), "r"((a)[1]), "r"((a)[2]), "r"((a)[3]), "r"((b)[0]), "r"((b)[1]))

// smem tiles (bytes): A [128 m][72 halfs] pitch 144B ((9r+c)%8 bijective);
//                     B [64 k][264 halfs] pitch 528B ((33r+c)%8 bijective)
#define APITCH   144
#define BPITCH   528
#define A_TILE   (128*APITCH)              // 18432
#define B_TILE   (64*BPITCH)               // 33792
#define STAGE    (A_TILE + B_TILE)         // 52224
#define NSTAGE   3
#define SM_A(s)  ((s)*STAGE)
#define SM_B(s)  ((s)*STAGE + A_TILE)
#define SMEM_MM  (NSTAGE*STAGE)            // 156672

// ---------------- fused prep: fp32 -> fp16 for all operands + lang decode ----------------
#define R_FEAT  (MTOK*EDIM/4)
#define R_WSH   (EDIM*HDIM/4)
#define R_WG1   (NLANG*2*HDIM*HDIM/4)
#define R_TOTAL (2*R_FEAT + 2*R_WSH + R_WG1)
__global__ void __launch_bounds__(256) k_prep(
    const float* __restrict__ ner, const float* __restrict__ topf,
    const float* __restrict__ Wner, const float* __restrict__ Wtop,
    const float* __restrict__ Wg1, const int* __restrict__ lp)
{
    int i = blockIdx.x * blockDim.x + threadIdx.x;
    if (i == 0) {
        int m = 0;
        #pragma unroll
        for (int j = 1; j < 16; j += 2) m |= lp[j];
        bool is64 = (m == 0);
        for (int b = 0; b < NB; b++) d_lang[b] = is64 ? lp[2*b] : lp[b];
    }
    const float* src; __half* dst; int off;
    if      (i < R_FEAT)                 { src = ner;  dst = d_nerH;  off = i; }
    else if (i < 2*R_FEAT)               { src = topf; dst = d_topH;  off = i - R_FEAT; }
    else if (i < 2*R_FEAT + R_WSH)       { src = Wner; dst = d_WnerH; off = i - 2*R_FEAT; }
    else if (i < 2*R_FEAT + 2*R_WSH)     { src = Wtop; dst = d_WtopH; off = i - 2*R_FEAT - R_WSH; }
    else                                 { src = Wg1;  dst = d_Wg1H;  off = i - 2*R_FEAT - 2*R_WSH; }
    float4 v = ((const float4*)src)[off];
    __half2* d2 = (__half2*)(dst + (size_t)off * 4);
    d2[0] = __floats2half2_rn(v.x, v.y);
    d2[1] = __floats2half2_rn(v.z, v.w);
}

// ---------------- fp16 GEMM: C[128 m, 256 n] tile; 8 warps, warp tile 64x64 -----------
// A[m][k] fp16, W[k][n] fp16 native; B frags via ldmatrix.trans; 3-stage cp.async ring.
template<int NK, bool GATE>
__global__ void __launch_bounds__(256, 1) k_mm_fp16(
    const __half* __restrict__ A0, const __half* __restrict__ A1,
    const __half* __restrict__ W0, const __half* __restrict__ W1,
    const float* __restrict__ bz0, const float* __restrict__ bz1,
    float* __restrict__ C0, float* __restrict__ C1)
{
    constexpr int K = NK * 64;
    extern __shared__ __align__(128) char smem[];
    const uint32_t sb = smem_u32(smem);
    const int tid = threadIdx.x, wid = tid >> 5, l = tid & 31;
    const int m0 = blockIdx.y * 128, n0 = blockIdx.x * 256;
    const int wm = (wid & 1) * 64, wn = (wid >> 1) * 64;

    const __half *Ah, *Wt; const float *bias; float *C;
    if (GATE) {
        int lang = d_lang[blockIdx.y >> 2];
        Ah = A0;
        Wt = W0 + (size_t)lang * (2*HDIM) * HDIM;
        bias = bz0 + lang * HDIM;
        C = C0;
    } else {
        bool z = (blockIdx.z != 0);
        Ah = z ? A1 : A0; Wt = z ? W1 : W0; bias = z ? bz1 : bz0; C = z ? C1 : C0;
    }

    const uint32_t laneA = (uint32_t)((l & 15) * APITCH + (l >> 4) * 16);
    const uint32_t laneB = (uint32_t)((l & 15) * BPITCH + (l >> 4) * 16);

    auto loadT = [&](int it, int stage) {
        const int kc = it * 64;
        const uint32_t aB = sb + SM_A(stage);
        const uint32_t bB = sb + SM_B(stage);
        #pragma unroll
        for (int i = 0; i < 4; i++) {          // A: 128 rows x 8 x 16B = 1024 chunks
            int idx = tid + i * 256;
            int r = idx >> 3, c = idx & 7;
            CP16(aB + r * APITCH + c * 16, Ah + (size_t)(m0 + r) * K + kc + c * 8);
        }
        #pragma unroll
        for (int i = 0; i < 8; i++) {          // B: 64 rows x 32 x 16B = 2048 chunks
            int idx = tid + i * 256;
            int r = idx >> 5, c = idx & 31;
            CP16(bB + r * BPITCH + c * 16, Wt + (size_t)(kc + r) * HDIM + n0 + c * 8);
        }
    };

    float acc[4][8][4] = {};

    // prologue: fill stages 0 and 1
    loadT(0, 0); CP_COMMIT();
    loadT(1, 1); CP_COMMIT();

    int stage = 0;
    int nstage = 2 % NSTAGE;
    for (int it = 0; it < NK; it++) {
        CP_WAIT(1);                            // my copies for stage `it` done
        __syncthreads();                       // all threads' copies visible; prev consumers done
        if (it + 2 < NK) loadT(it + 2, nstage);
        CP_COMMIT();

        const uint32_t aBase = sb + SM_A(stage) + (uint32_t)(wm * APITCH) + laneA;
        const uint32_t bBase = sb + SM_B(stage) + (uint32_t)(wn * 2) + laneB;
        #pragma unroll
        for (int ks = 0; ks < 4; ks++) {
            uint32_t af[4][4], bf[8][2];
            #pragma unroll
            for (int mt = 0; mt < 4; mt++)
                LDSM4(af[mt], aBase + mt * (16 * APITCH) + ks * 32);
            #pragma unroll
            for (int j = 0; j < 4; j++) {
                uint32_t t4[4];
                LDSM4T(t4, bBase + ks * (16 * BPITCH) + j * 32);
                bf[2*j][0] = t4[0]; bf[2*j][1] = t4[1];
                bf[2*j+1][0] = t4[2]; bf[2*j+1][1] = t4[3];
            }
            #pragma unroll
            for (int mt = 0; mt < 4; mt++)
                #pragma unroll
                for (int nt = 0; nt < 8; nt++)
                    MMA16816(acc[mt][nt], af[mt], bf[nt]);
        }
        stage  = (stage  + 1 == NSTAGE) ? 0 : stage + 1;
        nstage = (nstage + 1 == NSTAGE) ? 0 : nstage + 1;
    }

    // epilogue: + bias (fp32), store fp32
    #pragma unroll
    for (int mt = 0; mt < 4; mt++) {
        int r0 = m0 + wm + mt * 16 + (l >> 2);
        #pragma unroll
        for (int nt = 0; nt < 8; nt++) {
            int c = n0 + wn + nt * 8 + 2 * (l & 3);
            float bv0 = bias[c], bv1 = bias[c + 1];
            float2 v0 = { acc[mt][nt][0] + bv0, acc[mt][nt][1] + bv1 };
            float2 v1 = { acc[mt][nt][2] + bv0, acc[mt][nt][3] + bv1 };
            *(float2*)(C + (size_t)r0 * HDIM + c) = v0;
            *(float2*)(C + (size_t)(r0 + 8) * HDIM + c) = v1;
        }
    }
}

// ---------------- block reduction over 256 threads ----------------
__device__ __forceinline__ float blockSum256(float v) {
    #pragma unroll
    for (int o = 16; o > 0; o >>= 1) v += __shfl_xor_sync(0xffffffffu, v, o);
    __shared__ float sh[8];
    int w = threadIdx.x >> 5, l = threadIdx.x & 31;
    if (l == 0) sh[w] = v;
    __syncthreads();
    if (w == 0) {
        float x = (l < 8) ? sh[l] : 0.f;
        #pragma unroll
        for (int o = 4; o > 0; o >>= 1) x += __shfl_xor_sync(0xffffffffu, x, o);
        if (l == 0) sh[0] = x;
    }
    __syncthreads();
    float r = sh[0];
    __syncthreads();
    return r;
}

// ---------------- LN + ReLU in place (fp32) + fp16 copy into concat buffer ----------------
__global__ void __launch_bounds__(256) k_ln_relu2(
    const float* __restrict__ gN, const float* __restrict__ bN,
    const float* __restrict__ gT, const float* __restrict__ bT)
{
    int row = blockIdx.x;
    float* buf; const float* gamma; const float* beta; int hoff;
    if (row < MTOK) { buf = d_nerT; gamma = gN; beta = bN; hoff = 0; }
    else            { buf = d_topT; gamma = gT; beta = bT; hoff = HDIM; row -= MTOK; }
    float* x = buf + (size_t)row * HDIM;
    const int t = threadIdx.x;
    float4 v = *(const float4*)(x + t * 4);
    float s  = blockSum256(v.x + v.y + v.z + v.w);
    float mu = s * (1.f / HDIM);
    float d0 = v.x - mu, d1 = v.y - mu, d2 = v.z - mu, d3 = v.w - mu;
    float sq = blockSum256(d0*d0 + d1*d1 + d2*d2 + d3*d3);
    float inv = rsqrtf(sq * (1.f / HDIM) + 1e-5f);
    float4 g = *(const float4*)(gamma + t * 4);
    float4 b = *(const float4*)(beta  + t * 4);
    float4 o;
    o.x = fmaxf(d0*inv*g.x + b.x, 0.f);
    o.y = fmaxf(d1*inv*g.y + b.y, 0.f);
    o.z = fmaxf(d2*inv*g.z + b.z, 0.f);
    o.w = fmaxf(d3*inv*g.w + b.w, 0.f);
    *(float4*)(x + t * 4) = o;
    __half2* dh = (__half2*)(d_actH + (size_t)row * (2*HDIM) + hoff + t * 4);
    dh[0] = __floats2half2_rn(o.x, o.y);
    dh[1] = __floats2half2_rn(o.z, o.w);
}

// ---------------- final: LN+ReLU(hid) -> Wg2 dot -> sigmoid -> gate, write out ----------------
__global__ void __launch_bounds__(256) k_gate_finish(
    const float* __restrict__ gg, const float* __restrict__ bgv,
    const float* __restrict__ Wg2, const float* __restrict__ bg2,
    float* __restrict__ out)
{
    const int row  = blockIdx.x;
    const int lang = d_lang[row / SEQ];
    const int t    = threadIdx.x;
    const float* x = d_hid + (size_t)row * HDIM;
    float4 v = *(const float4*)(x + t * 4);
    float s  = blockSum256(v.x + v.y + v.z + v.w);
    float mu = s * (1.f / HDIM);
    float d0 = v.x - mu, d1 = v.y - mu, d2 = v.z - mu, d3 = v.w - mu;
    float sq = blockSum256(d0*d0 + d1*d1 + d2*d2 + d3*d3);
    float inv = rsqrtf(sq * (1.f / HDIM) + 1e-5f);
    float4 g = *(const float4*)(gg  + (size_t)lang * HDIM + t * 4);
    float4 b = *(const float4*)(bgv + (size_t)lang * HDIM + t * 4);
    float h0 = fmaxf(d0*inv*g.x + b.x, 0.f);
    float h1 = fmaxf(d1*inv*g.y + b.y, 0.f);
    float h2 = fmaxf(d2*inv*g.z + b.z, 0.f);
    float h3 = fmaxf(d3*inv*g.w + b.w, 0.f);
    const float* w2 = Wg2 + (size_t)lang * HDIM * 2 + (size_t)t * 8;
    float4 wa = *(const float4*)(w2);
    float4 wb = *(const float4*)(w2 + 4);
    float s0 = h0*wa.x + h1*wa.z + h2*wb.x + h3*wb.z;
    float s1 = h0*wa.y + h1*wa.w + h2*wb.y + h3*wb.w;
    s0 = blockSum256(s0);
    s1 = blockSum256(s1);
    float g0 = 1.f / (1.f + expf(-(s0 + bg2[lang*2 + 0])));
    float g1 = 1.f / (1.f + expf(-(s1 + bg2[lang*2 + 1])));
    size_t off = (size_t)row * HDIM + (size_t)t * 4;
    float4 nv = *(const float4*)(d_nerT + off);
    float4 tv = *(const float4*)(d_topT + off);
    float4 on = {nv.x*g0, nv.y*g0, nv.z*g0, nv.w*g0};
    float4 ot = {tv.x*g1, tv.y*g1, tv.z*g1, tv.w*g1};
    *(float4*)(out + off) = on;
    *(float4*)(out + (size_t)MTOK*HDIM + off) = ot;
}

extern "C" void kernel_launch(void* const* d_in, const int* in_sizes, int n_in,
                              void* d_out, int out_size)
{
    const float* ner    = (const float*)d_in[0];
    const float* topf   = (const float*)d_in[1];
    const int*   lang   = (const int*)d_in[2];
    const float* W_ner  = (const float*)d_in[3];
    const float* b_ner  = (const float*)d_in[4];
    const float* g_ner  = (const float*)d_in[5];
    const float* be_ner = (const float*)d_in[6];
    const float* W_top  = (const float*)d_in[7];
    const float* b_top  = (const float*)d_in[8];
    const float* g_top  = (const float*)d_in[9];
    const float* be_top = (const float*)d_in[10];
    const float* Wg1    = (const float*)d_in[11];
    const float* bg1    = (const float*)d_in[12];
    const float* gg     = (const float*)d_in[13];
    const float* bg     = (const float*)d_in[14];
    const float* Wg2    = (const float*)d_in[15];
    const float* bg2    = (const float*)d_in[16];
    float* out = (float*)d_out;

    __half *pNerH, *pTopH, *pWner, *pWtop, *pWg1, *pActH;
    float *pNerT, *pTopT, *pHid;
    cudaGetSymbolAddress((void**)&pNerH, d_nerH);
    cudaGetSymbolAddress((void**)&pTopH, d_topH);
    cudaGetSymbolAddress((void**)&pWner, d_WnerH);
    cudaGetSymbolAddress((void**)&pWtop, d_WtopH);
    cudaGetSymbolAddress((void**)&pWg1,  d_Wg1H);
    cudaGetSymbolAddress((void**)&pActH, d_actH);
    cudaGetSymbolAddress((void**)&pNerT, d_nerT);
    cudaGetSymbolAddress((void**)&pTopT, d_topT);
    cudaGetSymbolAddress((void**)&pHid,  d_hid);

    static bool attr_done = false;
    if (!attr_done) {
        cudaFuncSetAttribute(k_mm_fp16<12,false>, cudaFuncAttributeMaxDynamicSharedMemorySize, SMEM_MM);
        cudaFuncSetAttribute(k_mm_fp16<32,true>,  cudaFuncAttributeMaxDynamicSharedMemorySize, SMEM_MM);
        attr_done = true;
    }

    k_prep<<<R_TOTAL/256, 256>>>(ner, topf, W_ner, W_top, Wg1, lang);

    // shared transforms: both GEMMs in one launch (z = 0:ner, 1:topic)
    k_mm_fp16<12,false><<<dim3(HDIM/256, MTOK/128, 2), 256, SMEM_MM>>>(
        pNerH, pTopH, pWner, pWtop, b_ner, b_top, pNerT, pTopT);

    k_ln_relu2<<<2*MTOK, 256>>>(g_ner, be_ner, g_top, be_top);

    // gate MLP (K=2048), per-batch language selected
    k_mm_fp16<32,true><<<dim3(HDIM/256, MTOK/128, 1), 256, SMEM_MM>>>(
        pActH, nullptr, pWg1, nullptr, bg1, nullptr, pHid, nullptr);

    k_gate_finish<<<MTOK, 256>>>(gg, bg, Wg2, bg2, out);
}

// round 10
// speedup vs baseline: 6.0595x; 1.1006x over previous
#include <cuda_runtime.h>
#include <cuda_fp16.h>
#include <cstdint>

#define NB    16
#define SEQ   512
#define MTOK  8192
#define EDIM  768
#define HDIM  1024
#define NLANG 5

// ---------------- scratch (static device globals; allocation-free) ----------------
__device__ __align__(128) __half d_nerH [MTOK*EDIM];          // fp16 features [m][k]
__device__ __align__(128) __half d_topH [MTOK*EDIM];
__device__ __align__(128) __half d_WnerH[EDIM*HDIM];          // W fp16, native [k][n]
__device__ __align__(128) __half d_WtopH[EDIM*HDIM];
__device__ __align__(128) __half d_Wg1H [NLANG*2*HDIM*HDIM];  // Wg1 fp16 [l][k=2H][n=H]
__device__ __align__(128) __half d_actH [MTOK*2*HDIM];        // [ner | top] LN'd fp16
__device__ float d_nerT[MTOK*HDIM];
__device__ float d_topT[MTOK*HDIM];
__device__ float d_hid [MTOK*HDIM];
__device__ int   d_lang[NB];

// ---------------- PTX helpers ----------------
__device__ __forceinline__ uint32_t smem_u32(const void* p) {
    uint32_t a;
    asm("{ .reg .u64 t; cvta.to.shared.u64 t, %1; cvt.u32.u64 %0, t; }" : "=r"(a) : "l"(p));
    return a;
}
#define CP16(dst, src) asm volatile("cp.async.cg.shared.global [%0], [%1], 16;\n"::"r"(dst),"l"(src))
#define CP_COMMIT()    asm volatile("cp.async.commit_group;\n")
#define CP_WAIT(n)     asm volatile("cp.async.wait_group %0;\n"::"n"(n))

#define LDSM4(r, a) \
    asm volatile("ldmatrix.sync.aligned.m8n8.x4.shared.b16 {%0,%1,%2,%3}, [%4];" \
        : "=r"((r)[0]), "=r"((r)[1]), "=r"((r)[2]), "=r"((r)[3]) : "r"(a))
#define LDSM4T(r, a) \
    asm volatile("ldmatrix.sync.aligned.m8n8.x4.trans.shared.b16 {%0,%1,%2,%3}, [%4];" \
        : "=r"((r)[0]), "=r"((r)[1]), "=r"((r)[2]), "=r"((r)[3]) : "r"(a))

#define MMA16816(d, a, b) \
    asm volatile("mma.sync.aligned.m16n8k16.row.col.f32.f16.f16.f32 " \
        "{%0,%1,%2,%3}, {%4,%5,%6,%7}, {%8,%9}, {%0,%1,%2,%3};" \
        : "+f"((d)[0]), "+f"((d)[1]), "+f"((d)[2]), "+f"((d)[3]) \
        : "r"((a)[0]), "r"((a)[1]), "r"((a)[2]), "r"((a)[3]), "r"((b)[0]), "r"((b)[1]))

// smem tiles (bytes): A [128 m][72 halfs] pitch 144B ((9r+c)%8 bijective);
//                     B [64 k][136 halfs] pitch 272B ((17r+c)%8 = (r+c)%8 bijective)
#define APITCH   144
#define BPITCH   272
#define A_TILE   (128*APITCH)              // 18432
#define B_TILE   (64*BPITCH)               // 17408
#define STAGE    (A_TILE + B_TILE)         // 35840
#define NSTAGE   3
#define SM_A(s)  ((s)*STAGE)
#define SM_B(s)  ((s)*STAGE + A_TILE)
#define SMEM_MM  (NSTAGE*STAGE)            // 107520 -> 2 CTAs/SM

// ---------------- fused prep: fp32 -> fp16 for all operands + lang decode ----------------
#define R_FEAT  (MTOK*EDIM/4)
#define R_WSH   (EDIM*HDIM/4)
#define R_WG1   (NLANG*2*HDIM*HDIM/4)
#define R_TOTAL (2*R_FEAT + 2*R_WSH + R_WG1)
__global__ void __launch_bounds__(256) k_prep(
    const float* __restrict__ ner, const float* __restrict__ topf,
    const float* __restrict__ Wner, const float* __restrict__ Wtop,
    const float* __restrict__ Wg1, const int* __restrict__ lp)
{
    int i = blockIdx.x * blockDim.x + threadIdx.x;
    if (i == 0) {
        int m = 0;
        #pragma unroll
        for (int j = 1; j < 16; j += 2) m |= lp[j];
        bool is64 = (m == 0);
        for (int b = 0; b < NB; b++) d_lang[b] = is64 ? lp[2*b] : lp[b];
    }
    const float* src; __half* dst; int off;
    if      (i < R_FEAT)                 { src = ner;  dst = d_nerH;  off = i; }
    else if (i < 2*R_FEAT)               { src = topf; dst = d_topH;  off = i - R_FEAT; }
    else if (i < 2*R_FEAT + R_WSH)       { src = Wner; dst = d_WnerH; off = i - 2*R_FEAT; }
    else if (i < 2*R_FEAT + 2*R_WSH)     { src = Wtop; dst = d_WtopH; off = i - 2*R_FEAT - R_WSH; }
    else                                 { src = Wg1;  dst = d_Wg1H;  off = i - 2*R_FEAT - 2*R_WSH; }
    float4 v = ((const float4*)src)[off];
    __half2* d2 = (__half2*)(dst + (size_t)off * 4);
    d2[0] = __floats2half2_rn(v.x, v.y);
    d2[1] = __floats2half2_rn(v.z, v.w);
}

// ---------------- fp16 GEMM: C[128 m, 128 n] tile; 8 warps, warp tile 32x64 -----------
// 2 CTAs/SM (96 regs, 107.5KB smem) to kill wave quantization.
// A[m][k] fp16, W[k][n] fp16 native; B frags via ldmatrix.trans; 3-stage cp.async ring.
template<int NK, bool GATE>
__global__ void __launch_bounds__(256, 2) k_mm_fp16(
    const __half* __restrict__ A0, const __half* __restrict__ A1,
    const __half* __restrict__ W0, const __half* __restrict__ W1,
    const float* __restrict__ bz0, const float* __restrict__ bz1,
    float* __restrict__ C0, float* __restrict__ C1)
{
    constexpr int K = NK * 64;
    extern __shared__ __align__(128) char smem[];
    const uint32_t sb = smem_u32(smem);
    const int tid = threadIdx.x, wid = tid >> 5, l = tid & 31;
    const int m0 = blockIdx.y * 128, n0 = blockIdx.x * 128;
    const int wm = (wid & 3) * 32, wn = (wid >> 2) * 64;

    const __half *Ah, *Wt; const float *bias; float *C;
    if (GATE) {
        int lang = d_lang[blockIdx.y >> 2];
        Ah = A0;
        Wt = W0 + (size_t)lang * (2*HDIM) * HDIM;
        bias = bz0 + lang * HDIM;
        C = C0;
    } else {
        bool z = (blockIdx.z != 0);
        Ah = z ? A1 : A0; Wt = z ? W1 : W0; bias = z ? bz1 : bz0; C = z ? C1 : C0;
    }

    const uint32_t laneA = (uint32_t)((l & 15) * APITCH + (l >> 4) * 16);
    const uint32_t laneB = (uint32_t)((l & 15) * BPITCH + (l >> 4) * 16);

    auto loadT = [&](int it, int stage) {
        const int kc = it * 64;
        const uint32_t aB = sb + SM_A(stage);
        const uint32_t bB = sb + SM_B(stage);
        #pragma unroll
        for (int i = 0; i < 4; i++) {          // A: 128 rows x 8 x 16B = 1024 chunks
            int idx = tid + i * 256;
            int r = idx >> 3, c = idx & 7;
            CP16(aB + r * APITCH + c * 16, Ah + (size_t)(m0 + r) * K + kc + c * 8);
        }
        #pragma unroll
        for (int i = 0; i < 4; i++) {          // B: 64 rows x 16 x 16B = 1024 chunks
            int idx = tid + i * 256;
            int r = idx >> 4, c = idx & 15;
            CP16(bB + r * BPITCH + c * 16, Wt + (size_t)(kc + r) * HDIM + n0 + c * 8);
        }
    };

    float acc[2][8][4] = {};

    // prologue: fill stages 0 and 1
    loadT(0, 0); CP_COMMIT();
    loadT(1, 1); CP_COMMIT();

    int stage = 0;
    int nstage = 2 % NSTAGE;
    for (int it = 0; it < NK; it++) {
        CP_WAIT(1);                            // my copies for stage `it` done
        __syncthreads();                       // all threads' copies visible; prev consumers done
        if (it + 2 < NK) loadT(it + 2, nstage);
        CP_COMMIT();

        const uint32_t aBase = sb + SM_A(stage) + (uint32_t)(wm * APITCH) + laneA;
        const uint32_t bBase = sb + SM_B(stage) + (uint32_t)(wn * 2) + laneB;
        #pragma unroll
        for (int ks = 0; ks < 4; ks++) {
            uint32_t af[2][4], bf[8][2];
            #pragma unroll
            for (int mt = 0; mt < 2; mt++)
                LDSM4(af[mt], aBase + mt * (16 * APITCH) + ks * 32);
            #pragma unroll
            for (int j = 0; j < 4; j++) {
                uint32_t t4[4];
                LDSM4T(t4, bBase + ks * (16 * BPITCH) + j * 32);
                bf[2*j][0] = t4[0]; bf[2*j][1] = t4[1];
                bf[2*j+1][0] = t4[2]; bf[2*j+1][1] = t4[3];
            }
            #pragma unroll
            for (int mt = 0; mt < 2; mt++)
                #pragma unroll
                for (int nt = 0; nt < 8; nt++)
                    MMA16816(acc[mt][nt], af[mt], bf[nt]);
        }
        stage  = (stage  + 1 == NSTAGE) ? 0 : stage + 1;
        nstage = (nstage + 1 == NSTAGE) ? 0 : nstage + 1;
    }

    // epilogue: + bias (fp32), store fp32
    #pragma unroll
    for (int mt = 0; mt < 2; mt++) {
        int r0 = m0 + wm + mt * 16 + (l >> 2);
        #pragma unroll
        for (int nt = 0; nt < 8; nt++) {
            int c = n0 + wn + nt * 8 + 2 * (l & 3);
            float bv0 = bias[c], bv1 = bias[c + 1];
            float2 v0 = { acc[mt][nt][0] + bv0, acc[mt][nt][1] + bv1 };
            float2 v1 = { acc[mt][nt][2] + bv0, acc[mt][nt][3] + bv1 };
            *(float2*)(C + (size_t)r0 * HDIM + c) = v0;
            *(float2*)(C + (size_t)(r0 + 8) * HDIM + c) = v1;
        }
    }
}

// ---------------- block reduction over 256 threads ----------------
__device__ __forceinline__ float blockSum256(float v) {
    #pragma unroll
    for (int o = 16; o > 0; o >>= 1) v += __shfl_xor_sync(0xffffffffu, v, o);
    __shared__ float sh[8];
    int w = threadIdx.x >> 5, l = threadIdx.x & 31;
    if (l == 0) sh[w] = v;
    __syncthreads();
    if (w == 0) {
        float x = (l < 8) ? sh[l] : 0.f;
        #pragma unroll
        for (int o = 4; o > 0; o >>= 1) x += __shfl_xor_sync(0xffffffffu, x, o);
        if (l == 0) sh[0] = x;
    }
    __syncthreads();
    float r = sh[0];
    __syncthreads();
    return r;
}

// ---------------- LN + ReLU in place (fp32) + fp16 copy into concat buffer ----------------
__global__ void __launch_bounds__(256) k_ln_relu2(
    const float* __restrict__ gN, const float* __restrict__ bN,
    const float* __restrict__ gT, const float* __restrict__ bT)
{
    int row = blockIdx.x;
    float* buf; const float* gamma; const float* beta; int hoff;
    if (row < MTOK) { buf = d_nerT; gamma = gN; beta = bN; hoff = 0; }
    else            { buf = d_topT; gamma = gT; beta = bT; hoff = HDIM; row -= MTOK; }
    float* x = buf + (size_t)row * HDIM;
    const int t = threadIdx.x;
    float4 v = *(const float4*)(x + t * 4);
    float s  = blockSum256(v.x + v.y + v.z + v.w);
    float mu = s * (1.f / HDIM);
    float d0 = v.x - mu, d1 = v.y - mu, d2 = v.z - mu, d3 = v.w - mu;
    float sq = blockSum256(d0*d0 + d1*d1 + d2*d2 + d3*d3);
    float inv = rsqrtf(sq * (1.f / HDIM) + 1e-5f);
    float4 g = *(const float4*)(gamma + t * 4);
    float4 b = *(const float4*)(beta  + t * 4);
    float4 o;
    o.x = fmaxf(d0*inv*g.x + b.x, 0.f);
    o.y = fmaxf(d1*inv*g.y + b.y, 0.f);
    o.z = fmaxf(d2*inv*g.z + b.z, 0.f);
    o.w = fmaxf(d3*inv*g.w + b.w, 0.f);
    *(float4*)(x + t * 4) = o;
    __half2* dh = (__half2*)(d_actH + (size_t)row * (2*HDIM) + hoff + t * 4);
    dh[0] = __floats2half2_rn(o.x, o.y);
    dh[1] = __floats2half2_rn(o.z, o.w);
}

// ---------------- final: LN+ReLU(hid) -> Wg2 dot -> sigmoid -> gate, write out ----------------
__global__ void __launch_bounds__(256) k_gate_finish(
    const float* __restrict__ gg, const float* __restrict__ bgv,
    const float* __restrict__ Wg2, const float* __restrict__ bg2,
    float* __restrict__ out)
{
    const int row  = blockIdx.x;
    const int lang = d_lang[row / SEQ];
    const int t    = threadIdx.x;
    const float* x = d_hid + (size_t)row * HDIM;
    float4 v = *(const float4*)(x + t * 4);
    float s  = blockSum256(v.x + v.y + v.z + v.w);
    float mu = s * (1.f / HDIM);
    float d0 = v.x - mu, d1 = v.y - mu, d2 = v.z - mu, d3 = v.w - mu;
    float sq = blockSum256(d0*d0 + d1*d1 + d2*d2 + d3*d3);
    float inv = rsqrtf(sq * (1.f / HDIM) + 1e-5f);
    float4 g = *(const float4*)(gg  + (size_t)lang * HDIM + t * 4);
    float4 b = *(const float4*)(bgv + (size_t)lang * HDIM + t * 4);
    float h0 = fmaxf(d0*inv*g.x + b.x, 0.f);
    float h1 = fmaxf(d1*inv*g.y + b.y, 0.f);
    float h2 = fmaxf(d2*inv*g.z + b.z, 0.f);
    float h3 = fmaxf(d3*inv*g.w + b.w, 0.f);
    const float* w2 = Wg2 + (size_t)lang * HDIM * 2 + (size_t)t * 8;
    float4 wa = *(const float4*)(w2);
    float4 wb = *(const float4*)(w2 + 4);
    float s0 = h0*wa.x + h1*wa.z + h2*wb.x + h3*wb.z;
    float s1 = h0*wa.y + h1*wa.w + h2*wb.y + h3*wb.w;
    s0 = blockSum256(s0);
    s1 = blockSum256(s1);
    float g0 = 1.f / (1.f + expf(-(s0 + bg2[lang*2 + 0])));
    float g1 = 1.f / (1.f + expf(-(s1 + bg2[lang*2 + 1])));
    size_t off = (size_t)row * HDIM + (size_t)t * 4;
    float4 nv = *(const float4*)(d_nerT + off);
    float4 tv = *(const float4*)(d_topT + off);
    float4 on = {nv.x*g0, nv.y*g0, nv.z*g0, nv.w*g0};
    float4 ot = {tv.x*g1, tv.y*g1, tv.z*g1, tv.w*g1};
    *(float4*)(out + off) = on;
    *(float4*)(out + (size_t)MTOK*HDIM + off) = ot;
}

extern "C" void kernel_launch(void* const* d_in, const int* in_sizes, int n_in,
                              void* d_out, int out_size)
{
    const float* ner    = (const float*)d_in[0];
    const float* topf   = (const float*)d_in[1];
    const int*   lang   = (const int*)d_in[2];
    const float* W_ner  = (const float*)d_in[3];
    const float* b_ner  = (const float*)d_in[4];
    const float* g_ner  = (const float*)d_in[5];
    const float* be_ner = (const float*)d_in[6];
    const float* W_top  = (const float*)d_in[7];
    const float* b_top  = (const float*)d_in[8];
    const float* g_top  = (const float*)d_in[9];
    const float* be_top = (const float*)d_in[10];
    const float* Wg1    = (const float*)d_in[11];
    const float* bg1    = (const float*)d_in[12];
    const float* gg     = (const float*)d_in[13];
    const float* bg     = (const float*)d_in[14];
    const float* Wg2    = (const float*)d_in[15];
    const float* bg2    = (const float*)d_in[16];
    float* out = (float*)d_out;

    __half *pNerH, *pTopH, *pWner, *pWtop, *pWg1, *pActH;
    float *pNerT, *pTopT, *pHid;
    cudaGetSymbolAddress((void**)&pNerH, d_nerH);
    cudaGetSymbolAddress((void**)&pTopH, d_topH);
    cudaGetSymbolAddress((void**)&pWner, d_WnerH);
    cudaGetSymbolAddress((void**)&pWtop, d_WtopH);
    cudaGetSymbolAddress((void**)&pWg1,  d_Wg1H);
    cudaGetSymbolAddress((void**)&pActH, d_actH);
    cudaGetSymbolAddress((void**)&pNerT, d_nerT);
    cudaGetSymbolAddress((void**)&pTopT, d_topT);
    cudaGetSymbolAddress((void**)&pHid,  d_hid);

    static bool attr_done = false;
    if (!attr_done) {
        cudaFuncSetAttribute(k_mm_fp16<12,false>, cudaFuncAttributeMaxDynamicSharedMemorySize, SMEM_MM);
        cudaFuncSetAttribute(k_mm_fp16<32,true>,  cudaFuncAttributeMaxDynamicSharedMemorySize, SMEM_MM);
        attr_done = true;
    }

    k_prep<<<R_TOTAL/256, 256>>>(ner, topf, W_ner, W_top, Wg1, lang);

    // shared transforms: both GEMMs in one launch (z = 0:ner, 1:topic)
    k_mm_fp16<12,false><<<dim3(HDIM/128, MTOK/128, 2), 256, SMEM_MM>>>(
        pNerH, pTopH, pWner, pWtop, b_ner, b_top, pNerT, pTopT);

    k_ln_relu2<<<2*MTOK, 256>>>(g_ner, be_ner, g_top, be_top);

    // gate MLP (K=2048), per-batch language selected
    k_mm_fp16<32,true><<<dim3(HDIM/128, MTOK/128, 1), 256, SMEM_MM>>>(
        pActH, nullptr, pWg1, nullptr, bg1, nullptr, pHid, nullptr);

    k_gate_finish<<<MTOK, 256>>>(gg, bg, Wg2, bg2, out);
}

// round 11
// speedup vs baseline: 6.2859x; 1.0374x over previous
#include <cuda_runtime.h>
#include <cuda_fp16.h>
#include <cstdint>

#define NB    16
#define SEQ   512
#define MTOK  8192
#define EDIM  768
#define HDIM  1024
#define NLANG 5

// ---------------- scratch (static device globals; allocation-free) ----------------
__device__ __align__(128) __half d_nerH [MTOK*EDIM];          // fp16 features [m][k]
__device__ __align__(128) __half d_topH [MTOK*EDIM];
__device__ __align__(128) __half d_WnerH[EDIM*HDIM];          // W fp16, native [k][n]
__device__ __align__(128) __half d_WtopH[EDIM*HDIM];
__device__ __align__(128) __half d_Wg1H [NLANG*2*HDIM*HDIM];  // Wg1 fp16 [l][k=2H][n=H]
__device__ __align__(128) __half d_actH [MTOK*2*HDIM];        // [ner | top] LN'd fp16
__device__ float d_nerT[MTOK*HDIM];                            // pre-LN fp32 (LN input only)
__device__ float d_topT[MTOK*HDIM];
__device__ float d_hid [MTOK*HDIM];
__device__ int   d_lang[NB];

// ---------------- PTX helpers ----------------
__device__ __forceinline__ uint32_t smem_u32(const void* p) {
    uint32_t a;
    asm("{ .reg .u64 t; cvta.to.shared.u64 t, %1; cvt.u32.u64 %0, t; }" : "=r"(a) : "l"(p));
    return a;
}
#define CP16(dst, src) asm volatile("cp.async.cg.shared.global [%0], [%1], 16;\n"::"r"(dst),"l"(src))
#define CP_COMMIT()    asm volatile("cp.async.commit_group;\n")
#define CP_WAIT(n)     asm volatile("cp.async.wait_group %0;\n"::"n"(n))

#define LDSM4(r, a) \
    asm volatile("ldmatrix.sync.aligned.m8n8.x4.shared.b16 {%0,%1,%2,%3}, [%4];" \
        : "=r"((r)[0]), "=r"((r)[1]), "=r"((r)[2]), "=r"((r)[3]) : "r"(a))
#define LDSM4T(r, a) \
    asm volatile("ldmatrix.sync.aligned.m8n8.x4.trans.shared.b16 {%0,%1,%2,%3}, [%4];" \
        : "=r"((r)[0]), "=r"((r)[1]), "=r"((r)[2]), "=r"((r)[3]) : "r"(a))

#define MMA16816(d, a, b) \
    asm volatile("mma.sync.aligned.m16n8k16.row.col.f32.f16.f16.f32 " \
        "{%0,%1,%2,%3}, {%4,%5,%6,%7}, {%8,%9}, {%0,%1,%2,%3};" \
        : "+f"((d)[0]), "+f"((d)[1]), "+f"((d)[2]), "+f"((d)[3]) \
        : "r"((a)[0]), "r"((a)[1]), "r"((a)[2]), "r"((a)[3]), "r"((b)[0]), "r"((b)[1]))

// smem tiles (bytes): A [128 m][72 halfs] pitch 144B ((9r+c)%8 bijective);
//                     B [64 k][136 halfs] pitch 272B ((17r+c)%8 = (r+c)%8 bijective)
#define APITCH   144
#define BPITCH   272
#define A_TILE   (128*APITCH)              // 18432
#define B_TILE   (64*BPITCH)               // 17408
#define STAGE    (A_TILE + B_TILE)         // 35840
#define NSTAGE   3
#define SM_A(s)  ((s)*STAGE)
#define SM_B(s)  ((s)*STAGE + A_TILE)
#define SMEM_MM  (NSTAGE*STAGE)            // 107520 -> 2 CTAs/SM

// ---------------- warp reduction ----------------
__device__ __forceinline__ float warpSum(float v) {
    #pragma unroll
    for (int o = 16; o > 0; o >>= 1) v += __shfl_xor_sync(0xffffffffu, v, o);
    return v;
}

// ---------------- fused prep: fp32 -> fp16 for all operands + lang decode ----------------
#define R_FEAT  (MTOK*EDIM/4)
#define R_WSH   (EDIM*HDIM/4)
#define R_WG1   (NLANG*2*HDIM*HDIM/4)
#define R_TOTAL (2*R_FEAT + 2*R_WSH + R_WG1)
#define PREP_GRID (R_TOTAL/(256*4))
__global__ void __launch_bounds__(256) k_prep(
    const float* __restrict__ ner, const float* __restrict__ topf,
    const float* __restrict__ Wner, const float* __restrict__ Wtop,
    const float* __restrict__ Wg1, const int* __restrict__ lp)
{
    int gid = blockIdx.x * blockDim.x + threadIdx.x;
    if (gid == 0) {
        int m = 0;
        #pragma unroll
        for (int j = 1; j < 16; j += 2) m |= lp[j];
        bool is64 = (m == 0);
        for (int b = 0; b < NB; b++) d_lang[b] = is64 ? lp[2*b] : lp[b];
    }
    const int stride = PREP_GRID * 256;
    for (int i = gid; i < R_TOTAL; i += stride) {
        const float* src; __half* dst; int off;
        if      (i < R_FEAT)                 { src = ner;  dst = d_nerH;  off = i; }
        else if (i < 2*R_FEAT)               { src = topf; dst = d_topH;  off = i - R_FEAT; }
        else if (i < 2*R_FEAT + R_WSH)       { src = Wner; dst = d_WnerH; off = i - 2*R_FEAT; }
        else if (i < 2*R_FEAT + 2*R_WSH)     { src = Wtop; dst = d_WtopH; off = i - 2*R_FEAT - R_WSH; }
        else                                 { src = Wg1;  dst = d_Wg1H;  off = i - 2*R_FEAT - 2*R_WSH; }
        float4 v = ((const float4*)src)[off];
        __half2* d2 = (__half2*)(dst + (size_t)off * 4);
        d2[0] = __floats2half2_rn(v.x, v.y);
        d2[1] = __floats2half2_rn(v.z, v.w);
    }
}

// ---------------- fp16 GEMM: C[128 m, 128 n] tile; 8 warps, warp tile 32x64 -----------
// 2 CTAs/SM (128 regs, 107.5KB smem); 3-stage cp.async ring; B frags via ldmatrix.trans.
template<int NK, bool GATE>
__global__ void __launch_bounds__(256, 2) k_mm_fp16(
    const __half* __restrict__ A0, const __half* __restrict__ A1,
    const __half* __restrict__ W0, const __half* __restrict__ W1,
    const float* __restrict__ bz0, const float* __restrict__ bz1,
    float* __restrict__ C0, float* __restrict__ C1)
{
    constexpr int K = NK * 64;
    extern __shared__ __align__(128) char smem[];
    const uint32_t sb = smem_u32(smem);
    const int tid = threadIdx.x, wid = tid >> 5, l = tid & 31;
    const int m0 = blockIdx.y * 128, n0 = blockIdx.x * 128;
    const int wm = (wid & 3) * 32, wn = (wid >> 2) * 64;

    const __half *Ah, *Wt; const float *bias; float *C;
    if (GATE) {
        int lang = d_lang[blockIdx.y >> 2];
        Ah = A0;
        Wt = W0 + (size_t)lang * (2*HDIM) * HDIM;
        bias = bz0 + lang * HDIM;
        C = C0;
    } else {
        bool z = (blockIdx.z != 0);
        Ah = z ? A1 : A0; Wt = z ? W1 : W0; bias = z ? bz1 : bz0; C = z ? C1 : C0;
    }

    const uint32_t laneA = (uint32_t)((l & 15) * APITCH + (l >> 4) * 16);
    const uint32_t laneB = (uint32_t)((l & 15) * BPITCH + (l >> 4) * 16);

    auto loadT = [&](int it, int stage) {
        const int kc = it * 64;
        const uint32_t aB = sb + SM_A(stage);
        const uint32_t bB = sb + SM_B(stage);
        #pragma unroll
        for (int i = 0; i < 4; i++) {          // A: 128 rows x 8 x 16B = 1024 chunks
            int idx = tid + i * 256;
            int r = idx >> 3, c = idx & 7;
            CP16(aB + r * APITCH + c * 16, Ah + (size_t)(m0 + r) * K + kc + c * 8);
        }
        #pragma unroll
        for (int i = 0; i < 4; i++) {          // B: 64 rows x 16 x 16B = 1024 chunks
            int idx = tid + i * 256;
            int r = idx >> 4, c = idx & 15;
            CP16(bB + r * BPITCH + c * 16, Wt + (size_t)(kc + r) * HDIM + n0 + c * 8);
        }
    };

    float acc[2][8][4] = {};

    loadT(0, 0); CP_COMMIT();
    loadT(1, 1); CP_COMMIT();

    int stage = 0;
    int nstage = 2 % NSTAGE;
    for (int it = 0; it < NK; it++) {
        CP_WAIT(1);
        __syncthreads();
        if (it + 2 < NK) loadT(it + 2, nstage);
        CP_COMMIT();

        const uint32_t aBase = sb + SM_A(stage) + (uint32_t)(wm * APITCH) + laneA;
        const uint32_t bBase = sb + SM_B(stage) + (uint32_t)(wn * 2) + laneB;
        #pragma unroll
        for (int ks = 0; ks < 4; ks++) {
            uint32_t af[2][4], bf[8][2];
            #pragma unroll
            for (int mt = 0; mt < 2; mt++)
                LDSM4(af[mt], aBase + mt * (16 * APITCH) + ks * 32);
            #pragma unroll
            for (int j = 0; j < 4; j++) {
                uint32_t t4[4];
                LDSM4T(t4, bBase + ks * (16 * BPITCH) + j * 32);
                bf[2*j][0] = t4[0]; bf[2*j][1] = t4[1];
                bf[2*j+1][0] = t4[2]; bf[2*j+1][1] = t4[3];
            }
            #pragma unroll
            for (int mt = 0; mt < 2; mt++)
                #pragma unroll
                for (int nt = 0; nt < 8; nt++)
                    MMA16816(acc[mt][nt], af[mt], bf[nt]);
        }
        stage  = (stage  + 1 == NSTAGE) ? 0 : stage + 1;
        nstage = (nstage + 1 == NSTAGE) ? 0 : nstage + 1;
    }

    // epilogue: + bias (fp32), store fp32
    #pragma unroll
    for (int mt = 0; mt < 2; mt++) {
        int r0 = m0 + wm + mt * 16 + (l >> 2);
        #pragma unroll
        for (int nt = 0; nt < 8; nt++) {
            int c = n0 + wn + nt * 8 + 2 * (l & 3);
            float bv0 = bias[c], bv1 = bias[c + 1];
            float2 v0 = { acc[mt][nt][0] + bv0, acc[mt][nt][1] + bv1 };
            float2 v1 = { acc[mt][nt][2] + bv0, acc[mt][nt][3] + bv1 };
            *(float2*)(C + (size_t)r0 * HDIM + c) = v0;
            *(float2*)(C + (size_t)(r0 + 8) * HDIM + c) = v1;
        }
    }
}

// ---------------- LN + ReLU: warp-per-row, fp16 output only (d_actH) ----------------
// grid 2*MTOK/8; block 256 (8 warps). No __syncthreads.
__global__ void __launch_bounds__(256) k_ln_relu2(
    const float* __restrict__ gN, const float* __restrict__ bN,
    const float* __restrict__ gT, const float* __restrict__ bT)
{
    const int w = threadIdx.x >> 5, l = threadIdx.x & 31;
    const int row0 = blockIdx.x * 8 + w;
    const float *src, *gamma, *beta; int hoff, row;
    if (row0 < MTOK) { src = d_nerT; gamma = gN; beta = bN; hoff = 0;    row = row0; }
    else             { src = d_topT; gamma = gT; beta = bT; hoff = HDIM; row = row0 - MTOK; }
    const float4* x = (const float4*)(src + (size_t)row * HDIM);
    float4 v[8];
    float s = 0.f;
    #pragma unroll
    for (int i = 0; i < 8; i++) {
        v[i] = x[i*32 + l];
        s += v[i].x + v[i].y + v[i].z + v[i].w;
    }
    s = warpSum(s);
    float mu = s * (1.f / HDIM);
    float sq = 0.f;
    #pragma unroll
    for (int i = 0; i < 8; i++) {
        float a = v[i].x-mu, b = v[i].y-mu, c = v[i].z-mu, d = v[i].w-mu;
        sq += a*a + b*b + c*c + d*d;
    }
    sq = warpSum(sq);
    float inv = rsqrtf(sq * (1.f / HDIM) + 1e-5f);
    __half2* dh = (__half2*)(d_actH + (size_t)row * (2*HDIM) + hoff);
    #pragma unroll
    for (int i = 0; i < 8; i++) {
        int idx = i*32 + l;
        float4 g = ((const float4*)gamma)[idx];
        float4 b = ((const float4*)beta)[idx];
        float o0 = fmaxf((v[i].x-mu)*inv*g.x + b.x, 0.f);
        float o1 = fmaxf((v[i].y-mu)*inv*g.y + b.y, 0.f);
        float o2 = fmaxf((v[i].z-mu)*inv*g.z + b.z, 0.f);
        float o3 = fmaxf((v[i].w-mu)*inv*g.w + b.w, 0.f);
        dh[idx*2]   = __floats2half2_rn(o0, o1);
        dh[idx*2+1] = __floats2half2_rn(o2, o3);
    }
}

// ---------------- final: warp-per-row. LN+ReLU(hid)->Wg2->sigmoid->gate actH, write out --
// grid MTOK/8; block 256. No __syncthreads.
__global__ void __launch_bounds__(256) k_gate_finish(
    const float* __restrict__ gg, const float* __restrict__ bgv,
    const float* __restrict__ Wg2, const float* __restrict__ bg2,
    float* __restrict__ out)
{
    const int w = threadIdx.x >> 5, l = threadIdx.x & 31;
    const int row  = blockIdx.x * 8 + w;
    const int lang = d_lang[row >> 9];          // row / SEQ
    const float4* x = (const float4*)(d_hid + (size_t)row * HDIM);
    float4 v[8];
    float s = 0.f;
    #pragma unroll
    for (int i = 0; i < 8; i++) {
        v[i] = x[i*32 + l];
        s += v[i].x + v[i].y + v[i].z + v[i].w;
    }
    s = warpSum(s);
    float mu = s * (1.f / HDIM);
    float sq = 0.f;
    #pragma unroll
    for (int i = 0; i < 8; i++) {
        float a = v[i].x-mu, b = v[i].y-mu, c = v[i].z-mu, d = v[i].w-mu;
        sq += a*a + b*b + c*c + d*d;
    }
    sq = warpSum(sq);
    float inv = rsqrtf(sq * (1.f / HDIM) + 1e-5f);

    const float4* g4 = (const float4*)(gg  + (size_t)lang * HDIM);
    const float4* b4 = (const float4*)(bgv + (size_t)lang * HDIM);
    const float4* w4 = (const float4*)(Wg2 + (size_t)lang * HDIM * 2);
    float s0 = 0.f, s1 = 0.f;
    #pragma unroll
    for (int i = 0; i < 8; i++) {
        int idx = i*32 + l;
        float4 g = g4[idx], b = b4[idx];
        float h0 = fmaxf((v[i].x-mu)*inv*g.x + b.x, 0.f);
        float h1 = fmaxf((v[i].y-mu)*inv*g.y + b.y, 0.f);
        float h2 = fmaxf((v[i].z-mu)*inv*g.z + b.z, 0.f);
        float h3 = fmaxf((v[i].w-mu)*inv*g.w + b.w, 0.f);
        float4 wa = w4[idx*2], wb = w4[idx*2+1];
        s0 += h0*wa.x + h1*wa.z + h2*wb.x + h3*wb.z;
        s1 += h0*wa.y + h1*wa.w + h2*wb.y + h3*wb.w;
    }
    s0 = warpSum(s0);
    s1 = warpSum(s1);
    float g0 = 1.f / (1.f + expf(-(s0 + bg2[lang*2 + 0])));
    float g1 = 1.f / (1.f + expf(-(s1 + bg2[lang*2 + 1])));

    const __half2* an = (const __half2*)(d_actH + (size_t)row * (2*HDIM));
    const __half2* at = an + HDIM/2;
    float4* o0 = (float4*)(out + (size_t)row * HDIM);
    float4* o1 = (float4*)(out + (size_t)MTOK * HDIM + (size_t)row * HDIM);
    #pragma unroll
    for (int i = 0; i < 8; i++) {
        int idx = i*32 + l;
        float2 na = __half22float2(an[idx*2]), nb = __half22float2(an[idx*2+1]);
        float2 ta = __half22float2(at[idx*2]), tb = __half22float2(at[idx*2+1]);
        float4 on = { na.x*g0, na.y*g0, nb.x*g0, nb.y*g0 };
        float4 ot = { ta.x*g1, ta.y*g1, tb.x*g1, tb.y*g1 };
        o0[idx] = on;
        o1[idx] = ot;
    }
}

extern "C" void kernel_launch(void* const* d_in, const int* in_sizes, int n_in,
                              void* d_out, int out_size)
{
    const float* ner    = (const float*)d_in[0];
    const float* topf   = (const float*)d_in[1];
    const int*   lang   = (const int*)d_in[2];
    const float* W_ner  = (const float*)d_in[3];
    const float* b_ner  = (const float*)d_in[4];
    const float* g_ner  = (const float*)d_in[5];
    const float* be_ner = (const float*)d_in[6];
    const float* W_top  = (const float*)d_in[7];
    const float* b_top  = (const float*)d_in[8];
    const float* g_top  = (const float*)d_in[9];
    const float* be_top = (const float*)d_in[10];
    const float* Wg1    = (const float*)d_in[11];
    const float* bg1    = (const float*)d_in[12];
    const float* gg     = (const float*)d_in[13];
    const float* bg     = (const float*)d_in[14];
    const float* Wg2    = (const float*)d_in[15];
    const float* bg2    = (const float*)d_in[16];
    float* out = (float*)d_out;

    __half *pNerH, *pTopH, *pWner, *pWtop, *pWg1, *pActH;
    float *pNerT, *pTopT, *pHid;
    cudaGetSymbolAddress((void**)&pNerH, d_nerH);
    cudaGetSymbolAddress((void**)&pTopH, d_topH);
    cudaGetSymbolAddress((void**)&pWner, d_WnerH);
    cudaGetSymbolAddress((void**)&pWtop, d_WtopH);
    cudaGetSymbolAddress((void**)&pWg1,  d_Wg1H);
    cudaGetSymbolAddress((void**)&pActH, d_actH);
    cudaGetSymbolAddress((void**)&pNerT, d_nerT);
    cudaGetSymbolAddress((void**)&pTopT, d_topT);
    cudaGetSymbolAddress((void**)&pHid,  d_hid);

    static bool attr_done = false;
    if (!attr_done) {
        cudaFuncSetAttribute(k_mm_fp16<12,false>, cudaFuncAttributeMaxDynamicSharedMemorySize, SMEM_MM);
        cudaFuncSetAttribute(k_mm_fp16<32,true>,  cudaFuncAttributeMaxDynamicSharedMemorySize, SMEM_MM);
        attr_done = true;
    }

    k_prep<<<PREP_GRID, 256>>>(ner, topf, W_ner, W_top, Wg1, lang);

    // shared transforms: both GEMMs in one launch (z = 0:ner, 1:topic), fp32 pre-LN out
    k_mm_fp16<12,false><<<dim3(HDIM/128, MTOK/128, 2), 256, SMEM_MM>>>(
        pNerH, pTopH, pWner, pWtop, b_ner, b_top, pNerT, pTopT);

    k_ln_relu2<<<2*MTOK/8, 256>>>(g_ner, be_ner, g_top, be_top);

    // gate MLP (K=2048), per-batch language selected
    k_mm_fp16<32,true><<<dim3(HDIM/128, MTOK/128, 1), 256, SMEM_MM>>>(
        pActH, nullptr, pWg1, nullptr, bg1, nullptr, pHid, nullptr);

    k_gate_finish<<<MTOK/8, 256>>>(gg, bg, Wg2, bg2, out);
}

// round 12
// speedup vs baseline: 6.3171x; 1.0050x over previous
#include <cuda_runtime.h>
#include <cuda_fp16.h>
#include <cstdint>

#define NB    16
#define SEQ   512
#define MTOK  8192
#define EDIM  768
#define HDIM  1024
#define NLANG 5

// ---------------- scratch (static device globals; allocation-free) ----------------
__device__ __align__(128) __half d_nerH [MTOK*EDIM];          // fp16 features [m][k]
__device__ __align__(128) __half d_topH [MTOK*EDIM];
__device__ __align__(128) __half d_WnerH[EDIM*HDIM];          // W fp16, native [k][n]
__device__ __align__(128) __half d_WtopH[EDIM*HDIM];
__device__ __align__(128) __half d_Wg1H [NLANG*2*HDIM*HDIM];  // Wg1 fp16 [l][k=2H][n=H]
__device__ __align__(128) __half d_actH [MTOK*2*HDIM];        // [ner | top] LN'd fp16
__device__ __align__(128) __half d_preN [MTOK*HDIM];          // pre-LN fp16 (GEMM1 out)
__device__ __align__(128) __half d_preT [MTOK*HDIM];
__device__ __align__(128) __half d_hidH [MTOK*HDIM];          // gate hidden fp16
__device__ int   d_lang[NB];

// ---------------- PTX helpers ----------------
__device__ __forceinline__ uint32_t smem_u32(const void* p) {
    uint32_t a;
    asm("{ .reg .u64 t; cvta.to.shared.u64 t, %1; cvt.u32.u64 %0, t; }" : "=r"(a) : "l"(p));
    return a;
}
#define CP16(dst, src) asm volatile("cp.async.cg.shared.global [%0], [%1], 16;\n"::"r"(dst),"l"(src))
#define CP_COMMIT()    asm volatile("cp.async.commit_group;\n")
#define CP_WAIT(n)     asm volatile("cp.async.wait_group %0;\n"::"n"(n))

#define LDSM4(r, a) \
    asm volatile("ldmatrix.sync.aligned.m8n8.x4.shared.b16 {%0,%1,%2,%3}, [%4];" \
        : "=r"((r)[0]), "=r"((r)[1]), "=r"((r)[2]), "=r"((r)[3]) : "r"(a))
#define LDSM4T(r, a) \
    asm volatile("ldmatrix.sync.aligned.m8n8.x4.trans.shared.b16 {%0,%1,%2,%3}, [%4];" \
        : "=r"((r)[0]), "=r"((r)[1]), "=r"((r)[2]), "=r"((r)[3]) : "r"(a))

#define MMA16816(d, a, b) \
    asm volatile("mma.sync.aligned.m16n8k16.row.col.f32.f16.f16.f32 " \
        "{%0,%1,%2,%3}, {%4,%5,%6,%7}, {%8,%9}, {%0,%1,%2,%3};" \
        : "+f"((d)[0]), "+f"((d)[1]), "+f"((d)[2]), "+f"((d)[3]) \
        : "r"((a)[0]), "r"((a)[1]), "r"((a)[2]), "r"((a)[3]), "r"((b)[0]), "r"((b)[1]))

// smem tiles (bytes): A [128 m][72 halfs] pitch 144B; B [64 k][136 halfs] pitch 272B
#define APITCH   144
#define BPITCH   272
#define A_TILE   (128*APITCH)
#define B_TILE   (64*BPITCH)
#define STAGE    (A_TILE + B_TILE)         // 35840
#define NSTAGE   3
#define SM_A(s)  ((s)*STAGE)
#define SM_B(s)  ((s)*STAGE + A_TILE)
#define SMEM_MM  (NSTAGE*STAGE)            // 107520 -> 2 CTAs/SM

// ---------------- warp reduction ----------------
__device__ __forceinline__ float warpSum(float v) {
    #pragma unroll
    for (int o = 16; o > 0; o >>= 1) v += __shfl_xor_sync(0xffffffffu, v, o);
    return v;
}

// ---------------- fused prep: fp32 -> fp16 for all operands + lang decode ----------------
#define R_FEAT  (MTOK*EDIM/4)
#define R_WSH   (EDIM*HDIM/4)
#define R_WG1   (NLANG*2*HDIM*HDIM/4)
#define R_TOTAL (2*R_FEAT + 2*R_WSH + R_WG1)
#define PREP_GRID (R_TOTAL/(256*4))
__global__ void __launch_bounds__(256) k_prep(
    const float* __restrict__ ner, const float* __restrict__ topf,
    const float* __restrict__ Wner, const float* __restrict__ Wtop,
    const float* __restrict__ Wg1, const int* __restrict__ lp)
{
    int gid = blockIdx.x * blockDim.x + threadIdx.x;
    if (gid == 0) {
        int m = 0;
        #pragma unroll
        for (int j = 1; j < 16; j += 2) m |= lp[j];
        bool is64 = (m == 0);
        for (int b = 0; b < NB; b++) d_lang[b] = is64 ? lp[2*b] : lp[b];
    }
    const int stride = PREP_GRID * 256;
    for (int i = gid; i < R_TOTAL; i += stride) {
        const float* src; __half* dst; int off;
        if      (i < R_FEAT)                 { src = ner;  dst = d_nerH;  off = i; }
        else if (i < 2*R_FEAT)               { src = topf; dst = d_topH;  off = i - R_FEAT; }
        else if (i < 2*R_FEAT + R_WSH)       { src = Wner; dst = d_WnerH; off = i - 2*R_FEAT; }
        else if (i < 2*R_FEAT + 2*R_WSH)     { src = Wtop; dst = d_WtopH; off = i - 2*R_FEAT - R_WSH; }
        else                                 { src = Wg1;  dst = d_Wg1H;  off = i - 2*R_FEAT - 2*R_WSH; }
        float4 v = ((const float4*)src)[off];
        __half2* d2 = (__half2*)(dst + (size_t)off * 4);
        d2[0] = __floats2half2_rn(v.x, v.y);
        d2[1] = __floats2half2_rn(v.z, v.w);
    }
}

// ---------------- fp16 GEMM: C[128 m, 128 n] tile; 8 warps, warp tile 32x64 -----------
// fp32 accum + bias, fp16 output. 3-stage cp.async ring; B frags via ldmatrix.trans.
template<int NK, bool GATE>
__global__ void __launch_bounds__(256, 2) k_mm_fp16(
    const __half* __restrict__ A0, const __half* __restrict__ A1,
    const __half* __restrict__ W0, const __half* __restrict__ W1,
    const float* __restrict__ bz0, const float* __restrict__ bz1,
    __half* __restrict__ C0, __half* __restrict__ C1)
{
    constexpr int K = NK * 64;
    extern __shared__ __align__(128) char smem[];
    const uint32_t sb = smem_u32(smem);
    const int tid = threadIdx.x, wid = tid >> 5, l = tid & 31;
    const int m0 = blockIdx.y * 128, n0 = blockIdx.x * 128;
    const int wm = (wid & 3) * 32, wn = (wid >> 2) * 64;

    const __half *Ah, *Wt; const float *bias; __half *C;
    if (GATE) {
        int lang = d_lang[blockIdx.y >> 2];
        Ah = A0;
        Wt = W0 + (size_t)lang * (2*HDIM) * HDIM;
        bias = bz0 + lang * HDIM;
        C = C0;
    } else {
        bool z = (blockIdx.z != 0);
        Ah = z ? A1 : A0; Wt = z ? W1 : W0; bias = z ? bz1 : bz0; C = z ? C1 : C0;
    }

    const uint32_t laneA = (uint32_t)((l & 15) * APITCH + (l >> 4) * 16);
    const uint32_t laneB = (uint32_t)((l & 15) * BPITCH + (l >> 4) * 16);

    auto loadT = [&](int it, int stage) {
        const int kc = it * 64;
        const uint32_t aB = sb + SM_A(stage);
        const uint32_t bB = sb + SM_B(stage);
        #pragma unroll
        for (int i = 0; i < 4; i++) {          // A: 128 rows x 8 x 16B
            int idx = tid + i * 256;
            int r = idx >> 3, c = idx & 7;
            CP16(aB + r * APITCH + c * 16, Ah + (size_t)(m0 + r) * K + kc + c * 8);
        }
        #pragma unroll
        for (int i = 0; i < 4; i++) {          // B: 64 rows x 16 x 16B
            int idx = tid + i * 256;
            int r = idx >> 4, c = idx & 15;
            CP16(bB + r * BPITCH + c * 16, Wt + (size_t)(kc + r) * HDIM + n0 + c * 8);
        }
    };

    float acc[2][8][4] = {};

    loadT(0, 0); CP_COMMIT();
    loadT(1, 1); CP_COMMIT();

    int stage = 0;
    int nstage = 2 % NSTAGE;
    for (int it = 0; it < NK; it++) {
        CP_WAIT(1);
        __syncthreads();
        if (it + 2 < NK) loadT(it + 2, nstage);
        CP_COMMIT();

        const uint32_t aBase = sb + SM_A(stage) + (uint32_t)(wm * APITCH) + laneA;
        const uint32_t bBase = sb + SM_B(stage) + (uint32_t)(wn * 2) + laneB;
        #pragma unroll
        for (int ks = 0; ks < 4; ks++) {
            uint32_t af[2][4], bf[8][2];
            #pragma unroll
            for (int mt = 0; mt < 2; mt++)
                LDSM4(af[mt], aBase + mt * (16 * APITCH) + ks * 32);
            #pragma unroll
            for (int j = 0; j < 4; j++) {
                uint32_t t4[4];
                LDSM4T(t4, bBase + ks * (16 * BPITCH) + j * 32);
                bf[2*j][0] = t4[0]; bf[2*j][1] = t4[1];
                bf[2*j+1][0] = t4[2]; bf[2*j+1][1] = t4[3];
            }
            #pragma unroll
            for (int mt = 0; mt < 2; mt++)
                #pragma unroll
                for (int nt = 0; nt < 8; nt++)
                    MMA16816(acc[mt][nt], af[mt], bf[nt]);
        }
        stage  = (stage  + 1 == NSTAGE) ? 0 : stage + 1;
        nstage = (nstage + 1 == NSTAGE) ? 0 : nstage + 1;
    }

    // epilogue: + bias (fp32), store fp16
    #pragma unroll
    for (int mt = 0; mt < 2; mt++) {
        int r0 = m0 + wm + mt * 16 + (l >> 2);
        #pragma unroll
        for (int nt = 0; nt < 8; nt++) {
            int c = n0 + wn + nt * 8 + 2 * (l & 3);
            float bv0 = bias[c], bv1 = bias[c + 1];
            *(__half2*)(C + (size_t)r0 * HDIM + c) =
                __floats2half2_rn(acc[mt][nt][0] + bv0, acc[mt][nt][1] + bv1);
            *(__half2*)(C + (size_t)(r0 + 8) * HDIM + c) =
                __floats2half2_rn(acc[mt][nt][2] + bv0, acc[mt][nt][3] + bv1);
        }
    }
}

// ---------------- unpack helper: uint4 (8 halfs) -> 8 floats ----------------
__device__ __forceinline__ void unpack8(const uint4& r, float* f) {
    float2 p;
    p = __half22float2(*(const __half2*)&r.x); f[0] = p.x; f[1] = p.y;
    p = __half22float2(*(const __half2*)&r.y); f[2] = p.x; f[3] = p.y;
    p = __half22float2(*(const __half2*)&r.z); f[4] = p.x; f[5] = p.y;
    p = __half22float2(*(const __half2*)&r.w); f[6] = p.x; f[7] = p.y;
}

// ---------------- LN + ReLU: warp-per-row, fp16 in (pre) / fp16 out (actH) ----------------
// grid 2*MTOK/8; block 256 (8 warps). Each lane handles 4 chunks of 8 halfs.
__global__ void __launch_bounds__(256) k_ln_relu2(
    const float* __restrict__ gN, const float* __restrict__ bN,
    const float* __restrict__ gT, const float* __restrict__ bT)
{
    const int w = threadIdx.x >> 5, l = threadIdx.x & 31;
    const int row0 = blockIdx.x * 8 + w;
    const __half *src; const float *gamma, *beta; int hoff, row;
    if (row0 < MTOK) { src = d_preN; gamma = gN; beta = bN; hoff = 0;    row = row0; }
    else             { src = d_preT; gamma = gT; beta = bT; hoff = HDIM; row = row0 - MTOK; }
    const uint4* x = (const uint4*)(src + (size_t)row * HDIM);
    uint4 raw[4];
    float f[4][8];
    float s = 0.f;
    #pragma unroll
    for (int i = 0; i < 4; i++) {
        raw[i] = x[i*32 + l];
        unpack8(raw[i], f[i]);
        #pragma unroll
        for (int j = 0; j < 8; j++) s += f[i][j];
    }
    s = warpSum(s);
    float mu = s * (1.f / HDIM);
    float sq = 0.f;
    #pragma unroll
    for (int i = 0; i < 4; i++)
        #pragma unroll
        for (int j = 0; j < 8; j++) { float d = f[i][j] - mu; sq += d*d; }
    sq = warpSum(sq);
    float inv = rsqrtf(sq * (1.f / HDIM) + 1e-5f);
    uint4* dh = (uint4*)(d_actH + (size_t)row * (2*HDIM) + hoff);
    const float4* g4 = (const float4*)gamma;
    const float4* b4 = (const float4*)beta;
    #pragma unroll
    for (int i = 0; i < 4; i++) {
        int e = (i*32 + l) * 2;            // float4 index (4 floats each)
        float o[8];
        #pragma unroll
        for (int h = 0; h < 2; h++) {
            float4 g = g4[e + h], b = b4[e + h];
            o[h*4+0] = fmaxf((f[i][h*4+0]-mu)*inv*g.x + b.x, 0.f);
            o[h*4+1] = fmaxf((f[i][h*4+1]-mu)*inv*g.y + b.y, 0.f);
            o[h*4+2] = fmaxf((f[i][h*4+2]-mu)*inv*g.z + b.z, 0.f);
            o[h*4+3] = fmaxf((f[i][h*4+3]-mu)*inv*g.w + b.w, 0.f);
        }
        uint4 ov;
        *(__half2*)&ov.x = __floats2half2_rn(o[0], o[1]);
        *(__half2*)&ov.y = __floats2half2_rn(o[2], o[3]);
        *(__half2*)&ov.z = __floats2half2_rn(o[4], o[5]);
        *(__half2*)&ov.w = __floats2half2_rn(o[6], o[7]);
        dh[i*32 + l] = ov;
    }
}

// ---------------- final: warp-per-row. LN+ReLU(hidH fp16)->Wg2->sigmoid->gate actH ----
__global__ void __launch_bounds__(256) k_gate_finish(
    const float* __restrict__ gg, const float* __restrict__ bgv,
    const float* __restrict__ Wg2, const float* __restrict__ bg2,
    float* __restrict__ out)
{
    const int w = threadIdx.x >> 5, l = threadIdx.x & 31;
    const int row  = blockIdx.x * 8 + w;
    const int lang = d_lang[row >> 9];
    const uint4* x = (const uint4*)(d_hidH + (size_t)row * HDIM);
    float f[4][8];
    float s = 0.f;
    #pragma unroll
    for (int i = 0; i < 4; i++) {
        uint4 raw = x[i*32 + l];
        unpack8(raw, f[i]);
        #pragma unroll
        for (int j = 0; j < 8; j++) s += f[i][j];
    }
    s = warpSum(s);
    float mu = s * (1.f / HDIM);
    float sq = 0.f;
    #pragma unroll
    for (int i = 0; i < 4; i++)
        #pragma unroll
        for (int j = 0; j < 8; j++) { float d = f[i][j] - mu; sq += d*d; }
    sq = warpSum(sq);
    float inv = rsqrtf(sq * (1.f / HDIM) + 1e-5f);

    const float4* g4 = (const float4*)(gg  + (size_t)lang * HDIM);
    const float4* b4 = (const float4*)(bgv + (size_t)lang * HDIM);
    const float4* w4 = (const float4*)(Wg2 + (size_t)lang * HDIM * 2);
    float s0 = 0.f, s1 = 0.f;
    #pragma unroll
    for (int i = 0; i < 4; i++) {
        int e = (i*32 + l) * 2;
        #pragma unroll
        for (int h = 0; h < 2; h++) {
            float4 g = g4[e + h], b = b4[e + h];
            float h0 = fmaxf((f[i][h*4+0]-mu)*inv*g.x + b.x, 0.f);
            float h1 = fmaxf((f[i][h*4+1]-mu)*inv*g.y + b.y, 0.f);
            float h2 = fmaxf((f[i][h*4+2]-mu)*inv*g.z + b.z, 0.f);
            float h3 = fmaxf((f[i][h*4+3]-mu)*inv*g.w + b.w, 0.f);
            // Wg2 rows (e+h)*2 .. : each float4 = 2 h-entries (k0,k1)
            float4 wa = w4[(e + h)*2], wb = w4[(e + h)*2 + 1];
            s0 += h0*wa.x + h1*wa.z + h2*wb.x + h3*wb.z;
            s1 += h0*wa.y + h1*wa.w + h2*wb.y + h3*wb.w;
        }
    }
    s0 = warpSum(s0);
    s1 = warpSum(s1);
    float g0 = 1.f / (1.f + expf(-(s0 + bg2[lang*2 + 0])));
    float g1 = 1.f / (1.f + expf(-(s1 + bg2[lang*2 + 1])));

    const uint4* an = (const uint4*)(d_actH + (size_t)row * (2*HDIM));
    const uint4* at = (const uint4*)(d_actH + (size_t)row * (2*HDIM) + HDIM);
    float4* o0 = (float4*)(out + (size_t)row * HDIM);
    float4* o1 = (float4*)(out + (size_t)MTOK * HDIM + (size_t)row * HDIM);
    #pragma unroll
    for (int i = 0; i < 4; i++) {
        int idx = i*32 + l;
        float na[8], ta[8];
        unpack8(an[idx], na);
        unpack8(at[idx], ta);
        o0[idx*2]   = make_float4(na[0]*g0, na[1]*g0, na[2]*g0, na[3]*g0);
        o0[idx*2+1] = make_float4(na[4]*g0, na[5]*g0, na[6]*g0, na[7]*g0);
        o1[idx*2]   = make_float4(ta[0]*g1, ta[1]*g1, ta[2]*g1, ta[3]*g1);
        o1[idx*2+1] = make_float4(ta[4]*g1, ta[5]*g1, ta[6]*g1, ta[7]*g1);
    }
}

extern "C" void kernel_launch(void* const* d_in, const int* in_sizes, int n_in,
                              void* d_out, int out_size)
{
    const float* ner    = (const float*)d_in[0];
    const float* topf   = (const float*)d_in[1];
    const int*   lang   = (const int*)d_in[2];
    const float* W_ner  = (const float*)d_in[3];
    const float* b_ner  = (const float*)d_in[4];
    const float* g_ner  = (const float*)d_in[5];
    const float* be_ner = (const float*)d_in[6];
    const float* W_top  = (const float*)d_in[7];
    const float* b_top  = (const float*)d_in[8];
    const float* g_top  = (const float*)d_in[9];
    const float* be_top = (const float*)d_in[10];
    const float* Wg1    = (const float*)d_in[11];
    const float* bg1    = (const float*)d_in[12];
    const float* gg     = (const float*)d_in[13];
    const float* bg     = (const float*)d_in[14];
    const float* Wg2    = (const float*)d_in[15];
    const float* bg2    = (const float*)d_in[16];
    float* out = (float*)d_out;

    __half *pNerH, *pTopH, *pWner, *pWtop, *pWg1, *pActH, *pPreN, *pPreT, *pHidH;
    cudaGetSymbolAddress((void**)&pNerH, d_nerH);
    cudaGetSymbolAddress((void**)&pTopH, d_topH);
    cudaGetSymbolAddress((void**)&pWner, d_WnerH);
    cudaGetSymbolAddress((void**)&pWtop, d_WtopH);
    cudaGetSymbolAddress((void**)&pWg1,  d_Wg1H);
    cudaGetSymbolAddress((void**)&pActH, d_actH);
    cudaGetSymbolAddress((void**)&pPreN, d_preN);
    cudaGetSymbolAddress((void**)&pPreT, d_preT);
    cudaGetSymbolAddress((void**)&pHidH, d_hidH);

    static bool attr_done = false;
    if (!attr_done) {
        cudaFuncSetAttribute(k_mm_fp16<12,false>, cudaFuncAttributeMaxDynamicSharedMemorySize, SMEM_MM);
        cudaFuncSetAttribute(k_mm_fp16<32,true>,  cudaFuncAttributeMaxDynamicSharedMemorySize, SMEM_MM);
        attr_done = true;
    }

    k_prep<<<PREP_GRID, 256>>>(ner, topf, W_ner, W_top, Wg1, lang);

    // shared transforms: both GEMMs in one launch (z = 0:ner, 1:topic), fp16 pre-LN out
    k_mm_fp16<12,false><<<dim3(HDIM/128, MTOK/128, 2), 256, SMEM_MM>>>(
        pNerH, pTopH, pWner, pWtop, b_ner, b_top, pPreN, pPreT);

    k_ln_relu2<<<2*MTOK/8, 256>>>(g_ner, be_ner, g_top, be_top);

    // gate MLP (K=2048), per-batch language selected, fp16 hidden out
    k_mm_fp16<32,true><<<dim3(HDIM/128, MTOK/128, 1), 256, SMEM_MM>>>(
        pActH, nullptr, pWg1, nullptr, bg1, nullptr, pHidH, nullptr);

    k_gate_finish<<<MTOK/8, 256>>>(gg, bg, Wg2, bg2, out);
}